// round 8
// baseline (speedup 1.0000x reference)
#include <cuda_runtime.h>
#include <cuda_bf16.h>
#include <cstdint>
#include <math.h>

#define BATCH 8
#define DIM   512
#define HW    4096
#define IDIM  256

typedef __nv_bfloat16 bf16;

// ---------------- device scratch (static) ----------------
__device__ float g_QK[(size_t)BATCH * HW * 512];     // [n][0:256]=phi, [256:512]=theta (fp32)
__device__ bf16  g_Eh[(size_t)BATCH * HW * HW];      // exp(scores) hi/lo planes
__device__ bf16  g_El[(size_t)BATCH * HW * HW];
__device__ float g_part[(size_t)BATCH * HW * 32];    // per-CTA row partial sums
__device__ float g_inv[(size_t)BATCH * HW];          // 1 / rowsum
__device__ bf16  g_Fth[(size_t)BATCH * HW * DIM];    // F^T [b][n][c]
__device__ bf16  g_Ftl[(size_t)BATCH * HW * DIM];
__device__ bf16  g_Fh[(size_t)BATCH * DIM * HW];     // F [b][c][m]
__device__ bf16  g_Fl[(size_t)BATCH * DIM * HW];
__device__ bf16  g_Qh[(size_t)BATCH * HW * IDIM];
__device__ bf16  g_Ql[(size_t)BATCH * HW * IDIM];
__device__ bf16  g_Kh[(size_t)BATCH * HW * IDIM];
__device__ bf16  g_Kl[(size_t)BATCH * HW * IDIM];
__device__ bf16  g_Mh[(size_t)BATCH * HW * DIM];     // attn out [b][n][c]
__device__ bf16  g_Ml[(size_t)BATCH * HW * DIM];
__device__ bf16  g_Wth[(size_t)DIM * DIM];           // W^T [d][c]
__device__ bf16  g_Wtl[(size_t)DIM * DIM];
__device__ bf16  g_PTh[(size_t)2 * IDIM * DIM];      // stacked [phi_w; theta_w] hi/lo
__device__ bf16  g_PTl[(size_t)2 * IDIM * DIM];

// ---------------- helpers ----------------
__device__ __forceinline__ uint32_t smem_u32(const void* p) {
    uint32_t a;
    asm("{ .reg .u64 t; cvta.to.shared.u64 t, %1; cvt.u32.u64 %0, t; }" : "=r"(a) : "l"(p));
    return a;
}
__device__ __forceinline__ void cp16(uint32_t d, const void* s) {
    asm volatile("cp.async.cg.shared.global [%0], [%1], 16;" :: "r"(d), "l"(s));
}
__device__ __forceinline__ void split2(float x, bf16& h, bf16& l) {
    h = __float2bfloat16_rn(x);
    l = __float2bfloat16_rn(x - __bfloat162float(h));
}

#define LDSM4(R, addr)                                                           \
    asm volatile("ldmatrix.sync.aligned.m8n8.x4.shared.b16 {%0,%1,%2,%3}, [%4];" \
        : "=r"((R)[0]), "=r"((R)[1]), "=r"((R)[2]), "=r"((R)[3]) : "r"(addr))

#define MMA_BF16(c, a, b0, b1)                                                   \
    asm volatile(                                                                \
        "mma.sync.aligned.m16n8k16.row.col.f32.bf16.bf16.f32 "                   \
        "{%0,%1,%2,%3}, {%4,%5,%6,%7}, {%8,%9}, {%0,%1,%2,%3};"                  \
        : "+f"((c)[0]), "+f"((c)[1]), "+f"((c)[2]), "+f"((c)[3])                 \
        : "r"((a)[0]), "r"((a)[1]), "r"((a)[2]), "r"((a)[3]),                    \
          "r"((b0)), "r"((b1)))

// BK=64: rows are 128B (8 x 16B granules). granule q of row r stored at q ^ (r&7).
// Stage layout: Ah @0, Al @16K, Bh @32K, Bl @48K; stage stride 64K, 2 stages.
#define STGB 65536
__device__ __forceinline__ void fill_pl(uint32_t dbase, const bf16* src, int Kdim, int tid) {
    #pragma unroll
    for (int t = 0; t < 4; t++) {
        int idx = tid + t * 256;
        int row = idx >> 3, q = idx & 7;
        cp16(dbase + row * 128 + ((q ^ (row & 7)) << 4),
             src + (size_t)row * Kdim + q * 8);
    }
}

// ================= bf16-split NT GEMM via mma.sync + ldmatrix =================
// C[m][n] = sum_k A[m][k]*B[n][k], A=Ah+Al, B=Bh+Bl (lo*lo dropped).
// CTA 128x128, 8 warps (2x4) of 64x32, BK=64, cp.async double buffer (128KB smem).
// mode 0: fp32 store   1: relu fp32 store
// mode 3: exp() + bf16 split store + row partial sums (k2/scores)
// mode 4: row scale by Inv + bf16 split store (k4/aggregate)
__global__ void __launch_bounds__(256) gemm_bf16(
    const bf16* __restrict__ Ah, const bf16* __restrict__ Al,
    const bf16* __restrict__ Bh, const bf16* __restrict__ Bl,
    float* __restrict__ C, bf16* __restrict__ Ch, bf16* __restrict__ Cl,
    float* __restrict__ Part, const float* __restrict__ Inv,
    int Kdim, int Ncols, size_t sA, size_t sB, size_t sC, int mode)
{
    extern __shared__ char smem[];
    const int tid  = threadIdx.x;
    const int lane = tid & 31, wid = tid >> 5;
    const int g = lane >> 2, tg = lane & 3;
    const int wm = wid >> 2, wn = wid & 3;
    const uint32_t sb = smem_u32(smem);

    const size_t aoff = blockIdx.z * sA + (size_t)blockIdx.y * 128 * Kdim;
    const size_t boff = blockIdx.z * sB + (size_t)blockIdx.x * 128 * Kdim;
    const bf16* pAh = Ah + aoff;
    const bf16* pAl = Al + aoff;
    const bf16* pBh = Bh + boff;
    const bf16* pBl = Bl + boff;

    float acc[4][4][4];
    #pragma unroll
    for (int i = 0; i < 4; i++)
        #pragma unroll
        for (int j = 0; j < 4; j++)
            #pragma unroll
            for (int e = 0; e < 4; e++) acc[i][j][e] = 0.f;

    const int NC = Kdim >> 6;                 // chunks of 64
    const int rb = lane & 15, gs = lane >> 4;
    const int swz = rb & 7;

    fill_pl(sb +     0, pAh, Kdim, tid);
    fill_pl(sb + 16384, pAl, Kdim, tid);
    fill_pl(sb + 32768, pBh, Kdim, tid);
    fill_pl(sb + 49152, pBl, Kdim, tid);
    asm volatile("cp.async.commit_group;");

    for (int c = 0; c < NC; c++) {
        if (c + 1 < NC) {
            uint32_t nb = sb + ((c + 1) & 1) * STGB;
            int ko = (c + 1) * 64;
            fill_pl(nb +     0, pAh + ko, Kdim, tid);
            fill_pl(nb + 16384, pAl + ko, Kdim, tid);
            fill_pl(nb + 32768, pBh + ko, Kdim, tid);
            fill_pl(nb + 49152, pBl + ko, Kdim, tid);
            asm volatile("cp.async.commit_group;");
            asm volatile("cp.async.wait_group 1;");
        } else {
            asm volatile("cp.async.wait_group 0;");
        }
        __syncthreads();

        uint32_t bb = sb + (c & 1) * STGB;
        #pragma unroll
        for (int s = 0; s < 4; s++) {
            const int gp = (((2 * s + gs) ^ swz) << 4);
            uint32_t ah[4][4], al[4][4], bh[2][4], bl[2][4];
            #pragma unroll
            for (int i = 0; i < 4; i++) {
                uint32_t ra = bb + (uint32_t)(wm * 64 + i * 16 + rb) * 128 + gp;
                LDSM4(ah[i], ra);
                LDSM4(al[i], ra + 16384);
            }
            #pragma unroll
            for (int t = 0; t < 2; t++) {
                uint32_t rba = bb + 32768 + (uint32_t)(wn * 32 + t * 16 + rb) * 128 + gp;
                LDSM4(bh[t], rba);
                LDSM4(bl[t], rba + 16384);
            }
            #pragma unroll
            for (int i = 0; i < 4; i++)
                #pragma unroll
                for (int j = 0; j < 4; j++) {
                    const int t = j >> 1, u = j & 1;
                    MMA_BF16(acc[i][j], ah[i], bh[t][u], bh[t][u + 2]);
                    MMA_BF16(acc[i][j], ah[i], bl[t][u], bl[t][u + 2]);
                    MMA_BF16(acc[i][j], al[i], bh[t][u], bh[t][u + 2]);
                }
        }
        __syncthreads();
    }

    // ---------------- epilogue ----------------
    const int row0 = blockIdx.y * 128 + wm * 64;
    const int col0 = blockIdx.x * 128 + wn * 32;
    const int bz = blockIdx.z;

    if (mode == 3) {
        float* spart = (float*)smem;   // [128][4]
        float rsum[4][2];
        #pragma unroll
        for (int i = 0; i < 4; i++) { rsum[i][0] = 0.f; rsum[i][1] = 0.f; }
        #pragma unroll
        for (int i = 0; i < 4; i++) {
            int r0 = row0 + i * 16 + g;
            #pragma unroll
            for (int j = 0; j < 4; j++) {
                int cc = col0 + j * 8 + tg * 2;
                float e0 = __expf(acc[i][j][0]);
                float e1 = __expf(acc[i][j][1]);
                float e2 = __expf(acc[i][j][2]);
                float e3 = __expf(acc[i][j][3]);
                rsum[i][0] += e0 + e1;
                rsum[i][1] += e2 + e3;
                size_t o0 = bz * sC + (size_t)r0 * Ncols + cc;
                size_t o1 = o0 + 8 * (size_t)Ncols;
                bf16 h0, l0, h1, l1;
                __nv_bfloat162 hh, ll;
                split2(e0, h0, l0); split2(e1, h1, l1);
                hh.x = h0; hh.y = h1; ll.x = l0; ll.y = l1;
                *reinterpret_cast<__nv_bfloat162*>(Ch + o0) = hh;
                *reinterpret_cast<__nv_bfloat162*>(Cl + o0) = ll;
                split2(e2, h0, l0); split2(e3, h1, l1);
                hh.x = h0; hh.y = h1; ll.x = l0; ll.y = l1;
                *reinterpret_cast<__nv_bfloat162*>(Ch + o1) = hh;
                *reinterpret_cast<__nv_bfloat162*>(Cl + o1) = ll;
            }
        }
        #pragma unroll
        for (int i = 0; i < 4; i++) {
            #pragma unroll
            for (int h = 0; h < 2; h++) {
                float v = rsum[i][h];
                v += __shfl_xor_sync(0xffffffffu, v, 1);
                v += __shfl_xor_sync(0xffffffffu, v, 2);
                if (tg == 0)
                    spart[(wm * 64 + i * 16 + g + h * 8) * 4 + wn] = v;
            }
        }
        __syncthreads();
        if (tid < 128) {
            float4 p = *reinterpret_cast<float4*>(spart + tid * 4);
            Part[((size_t)bz * HW + blockIdx.y * 128 + tid) * 32 + blockIdx.x] =
                p.x + p.y + p.z + p.w;
        }
        return;
    }

    #pragma unroll
    for (int i = 0; i < 4; i++) {
        int r0 = row0 + i * 16 + g;
        float inv0 = 1.f, inv1 = 1.f;
        if (mode == 4) {
            inv0 = Inv[(size_t)bz * HW + r0];
            inv1 = Inv[(size_t)bz * HW + r0 + 8];
        }
        #pragma unroll
        for (int j = 0; j < 4; j++) {
            int cc = col0 + j * 8 + tg * 2;
            if (mode == 4) {
                size_t o0 = bz * sC + (size_t)r0 * Ncols + cc;
                size_t o1 = o0 + 8 * (size_t)Ncols;
                bf16 h0, l0, h1, l1;
                __nv_bfloat162 hh, ll;
                split2(acc[i][j][0] * inv0, h0, l0);
                split2(acc[i][j][1] * inv0, h1, l1);
                hh.x = h0; hh.y = h1; ll.x = l0; ll.y = l1;
                *reinterpret_cast<__nv_bfloat162*>(Ch + o0) = hh;
                *reinterpret_cast<__nv_bfloat162*>(Cl + o0) = ll;
                split2(acc[i][j][2] * inv1, h0, l0);
                split2(acc[i][j][3] * inv1, h1, l1);
                hh.x = h0; hh.y = h1; ll.x = l0; ll.y = l1;
                *reinterpret_cast<__nv_bfloat162*>(Ch + o1) = hh;
                *reinterpret_cast<__nv_bfloat162*>(Cl + o1) = ll;
            } else {
                float* b0 = C + bz * sC + (size_t)r0 * Ncols + cc;
                float* b1 = b0 + 8 * (size_t)Ncols;
                float2 v0, v1;
                v0.x = acc[i][j][0]; v0.y = acc[i][j][1];
                v1.x = acc[i][j][2]; v1.y = acc[i][j][3];
                if (mode == 1) {
                    v0.x = fmaxf(v0.x, 0.f); v0.y = fmaxf(v0.y, 0.f);
                    v1.x = fmaxf(v1.x, 0.f); v1.y = fmaxf(v1.y, 0.f);
                }
                *reinterpret_cast<float2*>(b0) = v0;
                *reinterpret_cast<float2*>(b1) = v1;
            }
        }
    }
}

// ---------------- inv rowsum ----------------
__global__ void __launch_bounds__(256) k3b_inv() {
    int wid = threadIdx.x >> 5, lane = threadIdx.x & 31;
    size_t rr = (size_t)blockIdx.x * 8 + wid;
    float v = g_part[rr * 32 + lane];
    #pragma unroll
    for (int o = 16; o > 0; o >>= 1) v += __shfl_xor_sync(0xffffffffu, v, o);
    if (lane == 0) g_inv[rr] = 1.0f / v;
}

// ---------------- transpose + bf16 split ----------------
__global__ void __launch_bounds__(256) trans_conv(const float* __restrict__ in,
                                                  bf16* __restrict__ oh, bf16* __restrict__ ol,
                                                  int R, int C) {
    __shared__ float t[32][33];
    int b = blockIdx.z;
    const float* ib = in + (size_t)b * R * C;
    size_t ob = (size_t)b * R * C;
    int c0 = blockIdx.x * 32, r0 = blockIdx.y * 32;
    int x = threadIdx.x, y = threadIdx.y;
    #pragma unroll
    for (int i = 0; i < 32; i += 8)
        t[y + i][x] = ib[(size_t)(r0 + y + i) * C + c0 + x];
    __syncthreads();
    #pragma unroll
    for (int i = 0; i < 32; i += 8) {
        float v = t[x][y + i];
        bf16 h, l; split2(v, h, l);
        size_t o = ob + (size_t)(c0 + y + i) * R + r0 + x;
        oh[o] = h; ol[o] = l;
    }
}

// ---------------- elementwise bf16 split ----------------
__global__ void __launch_bounds__(256) conv_split(const float* __restrict__ in,
                                                  bf16* __restrict__ oh, bf16* __restrict__ ol) {
    size_t i0 = ((size_t)blockIdx.x * 256 + threadIdx.x) * 4;
    float4 v = *reinterpret_cast<const float4*>(in + i0);
    bf16 h0, l0, h1, l1;
    __nv_bfloat162 hh, ll;
    split2(v.x, h0, l0); split2(v.y, h1, l1);
    hh.x = h0; hh.y = h1; ll.x = l0; ll.y = l1;
    *reinterpret_cast<__nv_bfloat162*>(oh + i0) = hh;
    *reinterpret_cast<__nv_bfloat162*>(ol + i0) = ll;
    split2(v.z, h0, l0); split2(v.w, h1, l1);
    hh.x = h0; hh.y = h1; ll.x = l0; ll.y = l1;
    *reinterpret_cast<__nv_bfloat162*>(oh + i0 + 2) = hh;
    *reinterpret_cast<__nv_bfloat162*>(ol + i0 + 2) = ll;
}

// ---------------- normalize phi/theta rows + split to bf16 planes ----------------
__global__ void __launch_bounds__(256) k1b_normalize() {
    size_t row = blockIdx.x;
    const float* qk = g_QK + row * 512;
    int t = threadIdx.x;
    float qv = qk[t], kv = qk[256 + t];
    float sq = qv * qv, sk = kv * kv;
    #pragma unroll
    for (int o = 16; o > 0; o >>= 1) {
        sq += __shfl_xor_sync(0xffffffffu, sq, o);
        sk += __shfl_xor_sync(0xffffffffu, sk, o);
    }
    __shared__ float sh[16];
    int w = t >> 5;
    if ((t & 31) == 0) { sh[w] = sq; sh[8 + w] = sk; }
    __syncthreads();
    float tq = 0.f, tk = 0.f;
    #pragma unroll
    for (int i = 0; i < 8; i++) { tq += sh[i]; tk += sh[8 + i]; }
    float qn = qv / sqrtf(tq);
    float kn = kv / sqrtf(tk);
    bf16 h, l;
    size_t o = row * IDIM + t;
    split2(qn, h, l); g_Qh[o] = h; g_Ql[o] = l;
    split2(kn, h, l); g_Kh[o] = h; g_Kl[o] = l;
}

// ---------------- launch ----------------
extern "C" void kernel_launch(void* const* d_in, const int* in_sizes, int n_in,
                              void* d_out, int out_size) {
    const float* feat    = (const float*)d_in[0];   // [8, 512, 64, 64]
    const float* phi_w   = (const float*)d_in[1];   // [256, 512]
    const float* theta_w = (const float*)d_in[2];   // [256, 512]
    const float* weight  = (const float*)d_in[3];   // [512, 512]
    float* out = (float*)d_out;                     // [8, 512, 64, 64]

    cudaFuncSetAttribute(gemm_bf16, cudaFuncAttributeMaxDynamicSharedMemorySize, 131072);

    float *QK, *Part, *Inv;
    bf16 *Eh, *El, *Fth, *Ftl, *Fh, *Fl, *Qh, *Ql, *Kh, *Kl, *Mh, *Ml;
    bf16 *Wth, *Wtl, *PTh, *PTl;
    cudaGetSymbolAddress((void**)&QK,   g_QK);
    cudaGetSymbolAddress((void**)&Part, g_part);
    cudaGetSymbolAddress((void**)&Inv,  g_inv);
    cudaGetSymbolAddress((void**)&Eh,   g_Eh);
    cudaGetSymbolAddress((void**)&El,   g_El);
    cudaGetSymbolAddress((void**)&Fth,  g_Fth);
    cudaGetSymbolAddress((void**)&Ftl,  g_Ftl);
    cudaGetSymbolAddress((void**)&Fh,   g_Fh);
    cudaGetSymbolAddress((void**)&Fl,   g_Fl);
    cudaGetSymbolAddress((void**)&Qh,   g_Qh);
    cudaGetSymbolAddress((void**)&Ql,   g_Ql);
    cudaGetSymbolAddress((void**)&Kh,   g_Kh);
    cudaGetSymbolAddress((void**)&Kl,   g_Kl);
    cudaGetSymbolAddress((void**)&Mh,   g_Mh);
    cudaGetSymbolAddress((void**)&Ml,   g_Ml);
    cudaGetSymbolAddress((void**)&Wth,  g_Wth);
    cudaGetSymbolAddress((void**)&Wtl,  g_Wtl);
    cudaGetSymbolAddress((void**)&PTh,  g_PTh);
    cudaGetSymbolAddress((void**)&PTl,  g_PTl);

    // prep: transposes + bf16 splits
    trans_conv<<<dim3(HW / 32, DIM / 32, BATCH), dim3(32, 8)>>>(feat, Fth, Ftl, DIM, HW);
    trans_conv<<<dim3(DIM / 32, DIM / 32, 1), dim3(32, 8)>>>(weight, Wth, Wtl, DIM, DIM);
    conv_split<<<(BATCH * DIM * HW) / 1024, 256>>>(feat, Fh, Fl);
    conv_split<<<(IDIM * DIM) / 1024, 256>>>(phi_w, PTh, PTl);
    conv_split<<<(IDIM * DIM) / 1024, 256>>>(theta_w, PTh + (size_t)IDIM * DIM, PTl + (size_t)IDIM * DIM);

    // k1 (merged): QK[n][j] = Ft[n][:] . [phi_w;theta_w][j][:]  (M=4096, N=512, K=512)
    gemm_bf16<<<dim3(512 / 128, HW / 128, BATCH), 256, 131072>>>(
        Fth, Ftl, PTh, PTl, QK, nullptr, nullptr, nullptr, nullptr,
        DIM, 512, (size_t)HW * DIM, 0, (size_t)HW * 512, 0);

    k1b_normalize<<<BATCH * HW, 256>>>();

    // k2: E[n][m] = exp(Qn . Km) + row partial sums  (M=N=4096, K=256)
    gemm_bf16<<<dim3(HW / 128, HW / 128, BATCH), 256, 131072>>>(
        Qh, Ql, Kh, Kl, nullptr, Eh, El, Part, nullptr,
        IDIM, HW, (size_t)HW * IDIM, (size_t)HW * IDIM, (size_t)HW * HW, 3);

    k3b_inv<<<HW * BATCH / 8, 256>>>();

    // k4: M[n][c] = (sum_m E[n][m] * F[c][m]) * inv[n]  (M=4096, N=512, K=4096)
    gemm_bf16<<<dim3(DIM / 128, HW / 128, BATCH), 256, 131072>>>(
        Eh, El, Fh, Fl, nullptr, Mh, Ml, nullptr, Inv,
        HW, DIM, (size_t)HW * HW, (size_t)DIM * HW, (size_t)HW * DIM, 4);

    // k5: out[d][n] = relu(Wt[d][:] . M[n][:])   (M=512, N=4096, K=512)
    gemm_bf16<<<dim3(HW / 128, DIM / 128, BATCH), 256, 131072>>>(
        Wth, Wtl, Mh, Ml, out, nullptr, nullptr, nullptr, nullptr,
        DIM, HW, 0, (size_t)HW * DIM, (size_t)DIM * HW, 1);
}

// round 9
// speedup vs baseline: 1.0485x; 1.0485x over previous
#include <cuda_runtime.h>
#include <cuda_bf16.h>
#include <cstdint>
#include <math.h>

#define BATCH 8
#define DIM   512
#define HW    4096
#define IDIM  256

typedef __nv_bfloat16 bf16;

// ---------------- device scratch (static) ----------------
__device__ float g_QK[(size_t)BATCH * HW * 512];     // [n][0:256]=phi, [256:512]=theta (fp32)
__device__ bf16  g_Eh[(size_t)BATCH * HW * HW];      // exp(scores) hi/lo planes
__device__ bf16  g_El[(size_t)BATCH * HW * HW];
__device__ float g_part[(size_t)BATCH * HW * 32];    // per-CTA row partial sums
__device__ float g_inv[(size_t)BATCH * HW];          // 1 / rowsum
__device__ bf16  g_Fth[(size_t)BATCH * HW * DIM];    // F^T [b][n][c]
__device__ bf16  g_Ftl[(size_t)BATCH * HW * DIM];
__device__ bf16  g_Fh[(size_t)BATCH * DIM * HW];     // F [b][c][m]
__device__ bf16  g_Fl[(size_t)BATCH * DIM * HW];
__device__ bf16  g_Qh[(size_t)BATCH * HW * IDIM];
__device__ bf16  g_Ql[(size_t)BATCH * HW * IDIM];
__device__ bf16  g_Kh[(size_t)BATCH * HW * IDIM];
__device__ bf16  g_Kl[(size_t)BATCH * HW * IDIM];
__device__ bf16  g_Mh[(size_t)BATCH * HW * DIM];     // attn out [b][n][c]
__device__ bf16  g_Ml[(size_t)BATCH * HW * DIM];
__device__ bf16  g_Wth[(size_t)DIM * DIM];           // W^T [d][c]
__device__ bf16  g_Wtl[(size_t)DIM * DIM];
__device__ bf16  g_PTh[(size_t)2 * IDIM * DIM];      // stacked [phi_w; theta_w] hi/lo
__device__ bf16  g_PTl[(size_t)2 * IDIM * DIM];

// ---------------- helpers ----------------
__device__ __forceinline__ uint32_t smem_u32(const void* p) {
    uint32_t a;
    asm("{ .reg .u64 t; cvta.to.shared.u64 t, %1; cvt.u32.u64 %0, t; }" : "=r"(a) : "l"(p));
    return a;
}
__device__ __forceinline__ void cp16(uint32_t d, const void* s) {
    asm volatile("cp.async.cg.shared.global [%0], [%1], 16;" :: "r"(d), "l"(s));
}
__device__ __forceinline__ void split2(float x, bf16& h, bf16& l) {
    h = __float2bfloat16_rn(x);
    l = __float2bfloat16_rn(x - __bfloat162float(h));
}

#define LDSM4(R, addr)                                                           \
    asm volatile("ldmatrix.sync.aligned.m8n8.x4.shared.b16 {%0,%1,%2,%3}, [%4];" \
        : "=r"((R)[0]), "=r"((R)[1]), "=r"((R)[2]), "=r"((R)[3]) : "r"(addr))

#define MMA_BF16(c, a, b0, b1)                                                   \
    asm volatile(                                                                \
        "mma.sync.aligned.m16n8k16.row.col.f32.bf16.bf16.f32 "                   \
        "{%0,%1,%2,%3}, {%4,%5,%6,%7}, {%8,%9}, {%0,%1,%2,%3};"                  \
        : "+f"((c)[0]), "+f"((c)[1]), "+f"((c)[2]), "+f"((c)[3])                 \
        : "r"((a)[0]), "r"((a)[1]), "r"((a)[2]), "r"((a)[3]),                    \
          "r"((b0)), "r"((b1)))

// BK=32: rows are 64B (4 x 16B granules). granule q of row r stored at q ^ ((r>>1)&3).
// Stage layout: Ah @0, Al @8K, Bh @16K, Bl @24K; stage stride 32K, 3 stages (96KB).
#define STGB 32768
__device__ __forceinline__ void fill_pl(uint32_t dbase, const bf16* src, int Kdim, int tid) {
    #pragma unroll
    for (int t = 0; t < 2; t++) {
        int idx = tid + t * 256;
        int row = idx >> 2, q = idx & 3;
        cp16(dbase + row * 64 + ((q ^ ((row >> 1) & 3)) << 4),
             src + (size_t)row * Kdim + q * 8);
    }
}
__device__ __forceinline__ void fill_stage(uint32_t nb, const bf16* pAh, const bf16* pAl,
                                           const bf16* pBh, const bf16* pBl,
                                           int ko, int Kdim, int tid) {
    fill_pl(nb +     0, pAh + ko, Kdim, tid);
    fill_pl(nb +  8192, pAl + ko, Kdim, tid);
    fill_pl(nb + 16384, pBh + ko, Kdim, tid);
    fill_pl(nb + 24576, pBl + ko, Kdim, tid);
    asm volatile("cp.async.commit_group;");
}

// ================= bf16-split NT GEMM via mma.sync + ldmatrix =================
// C[m][n] = sum_k A[m][k]*B[n][k], A=Ah+Al, B=Bh+Bl (lo*lo dropped).
// CTA 128x128, 8 warps (2x4) of 64x32, BK=32, cp.async 3-stage pipeline (96KB smem).
// mode 0: fp32 store   1: relu fp32 store
// mode 3: exp() + bf16 split store + row partial sums (k2/scores)
// mode 4: row scale by Inv + bf16 split store (k4/aggregate)
__global__ void __launch_bounds__(256) gemm_bf16(
    const bf16* __restrict__ Ah, const bf16* __restrict__ Al,
    const bf16* __restrict__ Bh, const bf16* __restrict__ Bl,
    float* __restrict__ C, bf16* __restrict__ Ch, bf16* __restrict__ Cl,
    float* __restrict__ Part, const float* __restrict__ Inv,
    int Kdim, int Ncols, size_t sA, size_t sB, size_t sC, int mode)
{
    extern __shared__ char smem[];
    const int tid  = threadIdx.x;
    const int lane = tid & 31, wid = tid >> 5;
    const int g = lane >> 2, tg = lane & 3;
    const int wm = wid >> 2, wn = wid & 3;
    const uint32_t sb = smem_u32(smem);

    const size_t aoff = blockIdx.z * sA + (size_t)blockIdx.y * 128 * Kdim;
    const size_t boff = blockIdx.z * sB + (size_t)blockIdx.x * 128 * Kdim;
    const bf16* pAh = Ah + aoff;
    const bf16* pAl = Al + aoff;
    const bf16* pBh = Bh + boff;
    const bf16* pBl = Bl + boff;

    float acc[4][4][4];
    #pragma unroll
    for (int i = 0; i < 4; i++)
        #pragma unroll
        for (int j = 0; j < 4; j++)
            #pragma unroll
            for (int e = 0; e < 4; e++) acc[i][j][e] = 0.f;

    const int NC = Kdim >> 5;                 // chunks of 32
    const int rb = lane & 15, gs = lane >> 4;
    const int swz = (rb >> 1) & 3;

    // prefetch stages 0,1
    fill_stage(sb, pAh, pAl, pBh, pBl, 0, Kdim, tid);
    if (NC > 1) fill_stage(sb + STGB, pAh, pAl, pBh, pBl, 32, Kdim, tid);

    int st = 0;
    for (int c = 0; c < NC; c++) {
        if (c + 2 < NC) {
            int s2 = (c + 2) % 3;
            fill_stage(sb + s2 * STGB, pAh, pAl, pBh, pBl, (c + 2) * 32, Kdim, tid);
            asm volatile("cp.async.wait_group 2;");
        } else if (c + 2 == NC) {
            asm volatile("cp.async.wait_group 1;");
        } else {
            asm volatile("cp.async.wait_group 0;");
        }
        __syncthreads();

        uint32_t bb = sb + st * STGB;
        #pragma unroll
        for (int s = 0; s < 2; s++) {
            const int gp = (((2 * s + gs) ^ swz) << 4);
            uint32_t ah[4][4], al[4][4], bh[2][4], bl[2][4];
            #pragma unroll
            for (int i = 0; i < 4; i++) {
                uint32_t ra = bb + (uint32_t)(wm * 64 + i * 16 + rb) * 64 + gp;
                LDSM4(ah[i], ra);
                LDSM4(al[i], ra + 8192);
            }
            #pragma unroll
            for (int t = 0; t < 2; t++) {
                uint32_t rba = bb + 16384 + (uint32_t)(wn * 32 + t * 16 + rb) * 64 + gp;
                LDSM4(bh[t], rba);
                LDSM4(bl[t], rba + 8192);
            }
            #pragma unroll
            for (int i = 0; i < 4; i++)
                #pragma unroll
                for (int j = 0; j < 4; j++) {
                    const int t = j >> 1, u = j & 1;
                    MMA_BF16(acc[i][j], ah[i], bh[t][u], bh[t][u + 2]);
                    MMA_BF16(acc[i][j], ah[i], bl[t][u], bl[t][u + 2]);
                    MMA_BF16(acc[i][j], al[i], bh[t][u], bh[t][u + 2]);
                }
        }
        __syncthreads();
        if (++st == 3) st = 0;
    }

    // ---------------- epilogue ----------------
    const int row0 = blockIdx.y * 128 + wm * 64;
    const int col0 = blockIdx.x * 128 + wn * 32;
    const int bz = blockIdx.z;

    if (mode == 3) {
        float* spart = (float*)smem;   // [128][4]
        float rsum[4][2];
        #pragma unroll
        for (int i = 0; i < 4; i++) { rsum[i][0] = 0.f; rsum[i][1] = 0.f; }
        #pragma unroll
        for (int i = 0; i < 4; i++) {
            int r0 = row0 + i * 16 + g;
            #pragma unroll
            for (int j = 0; j < 4; j++) {
                int cc = col0 + j * 8 + tg * 2;
                float e0 = __expf(acc[i][j][0]);
                float e1 = __expf(acc[i][j][1]);
                float e2 = __expf(acc[i][j][2]);
                float e3 = __expf(acc[i][j][3]);
                rsum[i][0] += e0 + e1;
                rsum[i][1] += e2 + e3;
                size_t o0 = bz * sC + (size_t)r0 * Ncols + cc;
                size_t o1 = o0 + 8 * (size_t)Ncols;
                bf16 h0, l0, h1, l1;
                __nv_bfloat162 hh, ll;
                split2(e0, h0, l0); split2(e1, h1, l1);
                hh.x = h0; hh.y = h1; ll.x = l0; ll.y = l1;
                *reinterpret_cast<__nv_bfloat162*>(Ch + o0) = hh;
                *reinterpret_cast<__nv_bfloat162*>(Cl + o0) = ll;
                split2(e2, h0, l0); split2(e3, h1, l1);
                hh.x = h0; hh.y = h1; ll.x = l0; ll.y = l1;
                *reinterpret_cast<__nv_bfloat162*>(Ch + o1) = hh;
                *reinterpret_cast<__nv_bfloat162*>(Cl + o1) = ll;
            }
        }
        #pragma unroll
        for (int i = 0; i < 4; i++) {
            #pragma unroll
            for (int h = 0; h < 2; h++) {
                float v = rsum[i][h];
                v += __shfl_xor_sync(0xffffffffu, v, 1);
                v += __shfl_xor_sync(0xffffffffu, v, 2);
                if (tg == 0)
                    spart[(wm * 64 + i * 16 + g + h * 8) * 4 + wn] = v;
            }
        }
        __syncthreads();
        if (tid < 128) {
            float4 p = *reinterpret_cast<float4*>(spart + tid * 4);
            Part[((size_t)bz * HW + blockIdx.y * 128 + tid) * 32 + blockIdx.x] =
                p.x + p.y + p.z + p.w;
        }
        return;
    }

    #pragma unroll
    for (int i = 0; i < 4; i++) {
        int r0 = row0 + i * 16 + g;
        float inv0 = 1.f, inv1 = 1.f;
        if (mode == 4) {
            inv0 = Inv[(size_t)bz * HW + r0];
            inv1 = Inv[(size_t)bz * HW + r0 + 8];
        }
        #pragma unroll
        for (int j = 0; j < 4; j++) {
            int cc = col0 + j * 8 + tg * 2;
            if (mode == 4) {
                size_t o0 = bz * sC + (size_t)r0 * Ncols + cc;
                size_t o1 = o0 + 8 * (size_t)Ncols;
                bf16 h0, l0, h1, l1;
                __nv_bfloat162 hh, ll;
                split2(acc[i][j][0] * inv0, h0, l0);
                split2(acc[i][j][1] * inv0, h1, l1);
                hh.x = h0; hh.y = h1; ll.x = l0; ll.y = l1;
                *reinterpret_cast<__nv_bfloat162*>(Ch + o0) = hh;
                *reinterpret_cast<__nv_bfloat162*>(Cl + o0) = ll;
                split2(acc[i][j][2] * inv1, h0, l0);
                split2(acc[i][j][3] * inv1, h1, l1);
                hh.x = h0; hh.y = h1; ll.x = l0; ll.y = l1;
                *reinterpret_cast<__nv_bfloat162*>(Ch + o1) = hh;
                *reinterpret_cast<__nv_bfloat162*>(Cl + o1) = ll;
            } else {
                float* b0 = C + bz * sC + (size_t)r0 * Ncols + cc;
                float* b1 = b0 + 8 * (size_t)Ncols;
                float2 v0, v1;
                v0.x = acc[i][j][0]; v0.y = acc[i][j][1];
                v1.x = acc[i][j][2]; v1.y = acc[i][j][3];
                if (mode == 1) {
                    v0.x = fmaxf(v0.x, 0.f); v0.y = fmaxf(v0.y, 0.f);
                    v1.x = fmaxf(v1.x, 0.f); v1.y = fmaxf(v1.y, 0.f);
                }
                *reinterpret_cast<float2*>(b0) = v0;
                *reinterpret_cast<float2*>(b1) = v1;
            }
        }
    }
}

// ---------------- inv rowsum ----------------
__global__ void __launch_bounds__(256) k3b_inv() {
    int wid = threadIdx.x >> 5, lane = threadIdx.x & 31;
    size_t rr = (size_t)blockIdx.x * 8 + wid;
    float v = g_part[rr * 32 + lane];
    #pragma unroll
    for (int o = 16; o > 0; o >>= 1) v += __shfl_xor_sync(0xffffffffu, v, o);
    if (lane == 0) g_inv[rr] = 1.0f / v;
}

// ---------------- transpose + bf16 split ----------------
__global__ void __launch_bounds__(256) trans_conv(const float* __restrict__ in,
                                                  bf16* __restrict__ oh, bf16* __restrict__ ol,
                                                  int R, int C) {
    __shared__ float t[32][33];
    int b = blockIdx.z;
    const float* ib = in + (size_t)b * R * C;
    size_t ob = (size_t)b * R * C;
    int c0 = blockIdx.x * 32, r0 = blockIdx.y * 32;
    int x = threadIdx.x, y = threadIdx.y;
    #pragma unroll
    for (int i = 0; i < 32; i += 8)
        t[y + i][x] = ib[(size_t)(r0 + y + i) * C + c0 + x];
    __syncthreads();
    #pragma unroll
    for (int i = 0; i < 32; i += 8) {
        float v = t[x][y + i];
        bf16 h, l; split2(v, h, l);
        size_t o = ob + (size_t)(c0 + y + i) * R + r0 + x;
        oh[o] = h; ol[o] = l;
    }
}

// ---------------- elementwise bf16 split ----------------
__global__ void __launch_bounds__(256) conv_split(const float* __restrict__ in,
                                                  bf16* __restrict__ oh, bf16* __restrict__ ol) {
    size_t i0 = ((size_t)blockIdx.x * 256 + threadIdx.x) * 4;
    float4 v = *reinterpret_cast<const float4*>(in + i0);
    bf16 h0, l0, h1, l1;
    __nv_bfloat162 hh, ll;
    split2(v.x, h0, l0); split2(v.y, h1, l1);
    hh.x = h0; hh.y = h1; ll.x = l0; ll.y = l1;
    *reinterpret_cast<__nv_bfloat162*>(oh + i0) = hh;
    *reinterpret_cast<__nv_bfloat162*>(ol + i0) = ll;
    split2(v.z, h0, l0); split2(v.w, h1, l1);
    hh.x = h0; hh.y = h1; ll.x = l0; ll.y = l1;
    *reinterpret_cast<__nv_bfloat162*>(oh + i0 + 2) = hh;
    *reinterpret_cast<__nv_bfloat162*>(ol + i0 + 2) = ll;
}

// ---------------- normalize phi/theta rows + split to bf16 planes ----------------
__global__ void __launch_bounds__(256) k1b_normalize() {
    size_t row = blockIdx.x;
    const float* qk = g_QK + row * 512;
    int t = threadIdx.x;
    float qv = qk[t], kv = qk[256 + t];
    float sq = qv * qv, sk = kv * kv;
    #pragma unroll
    for (int o = 16; o > 0; o >>= 1) {
        sq += __shfl_xor_sync(0xffffffffu, sq, o);
        sk += __shfl_xor_sync(0xffffffffu, sk, o);
    }
    __shared__ float sh[16];
    int w = t >> 5;
    if ((t & 31) == 0) { sh[w] = sq; sh[8 + w] = sk; }
    __syncthreads();
    float tq = 0.f, tk = 0.f;
    #pragma unroll
    for (int i = 0; i < 8; i++) { tq += sh[i]; tk += sh[8 + i]; }
    float qn = qv / sqrtf(tq);
    float kn = kv / sqrtf(tk);
    bf16 h, l;
    size_t o = row * IDIM + t;
    split2(qn, h, l); g_Qh[o] = h; g_Ql[o] = l;
    split2(kn, h, l); g_Kh[o] = h; g_Kl[o] = l;
}

// ---------------- launch ----------------
extern "C" void kernel_launch(void* const* d_in, const int* in_sizes, int n_in,
                              void* d_out, int out_size) {
    const float* feat    = (const float*)d_in[0];   // [8, 512, 64, 64]
    const float* phi_w   = (const float*)d_in[1];   // [256, 512]
    const float* theta_w = (const float*)d_in[2];   // [256, 512]
    const float* weight  = (const float*)d_in[3];   // [512, 512]
    float* out = (float*)d_out;                     // [8, 512, 64, 64]

    cudaFuncSetAttribute(gemm_bf16, cudaFuncAttributeMaxDynamicSharedMemorySize, 3 * STGB);

    float *QK, *Part, *Inv;
    bf16 *Eh, *El, *Fth, *Ftl, *Fh, *Fl, *Qh, *Ql, *Kh, *Kl, *Mh, *Ml;
    bf16 *Wth, *Wtl, *PTh, *PTl;
    cudaGetSymbolAddress((void**)&QK,   g_QK);
    cudaGetSymbolAddress((void**)&Part, g_part);
    cudaGetSymbolAddress((void**)&Inv,  g_inv);
    cudaGetSymbolAddress((void**)&Eh,   g_Eh);
    cudaGetSymbolAddress((void**)&El,   g_El);
    cudaGetSymbolAddress((void**)&Fth,  g_Fth);
    cudaGetSymbolAddress((void**)&Ftl,  g_Ftl);
    cudaGetSymbolAddress((void**)&Fh,   g_Fh);
    cudaGetSymbolAddress((void**)&Fl,   g_Fl);
    cudaGetSymbolAddress((void**)&Qh,   g_Qh);
    cudaGetSymbolAddress((void**)&Ql,   g_Ql);
    cudaGetSymbolAddress((void**)&Kh,   g_Kh);
    cudaGetSymbolAddress((void**)&Kl,   g_Kl);
    cudaGetSymbolAddress((void**)&Mh,   g_Mh);
    cudaGetSymbolAddress((void**)&Ml,   g_Ml);
    cudaGetSymbolAddress((void**)&Wth,  g_Wth);
    cudaGetSymbolAddress((void**)&Wtl,  g_Wtl);
    cudaGetSymbolAddress((void**)&PTh,  g_PTh);
    cudaGetSymbolAddress((void**)&PTl,  g_PTl);

    // prep: transposes + bf16 splits
    trans_conv<<<dim3(HW / 32, DIM / 32, BATCH), dim3(32, 8)>>>(feat, Fth, Ftl, DIM, HW);
    trans_conv<<<dim3(DIM / 32, DIM / 32, 1), dim3(32, 8)>>>(weight, Wth, Wtl, DIM, DIM);
    conv_split<<<(BATCH * DIM * HW) / 1024, 256>>>(feat, Fh, Fl);
    conv_split<<<(IDIM * DIM) / 1024, 256>>>(phi_w, PTh, PTl);
    conv_split<<<(IDIM * DIM) / 1024, 256>>>(theta_w, PTh + (size_t)IDIM * DIM, PTl + (size_t)IDIM * DIM);

    // k1 (merged): QK[n][j] = Ft[n][:] . [phi_w;theta_w][j][:]  (M=4096, N=512, K=512)
    gemm_bf16<<<dim3(512 / 128, HW / 128, BATCH), 256, 3 * STGB>>>(
        Fth, Ftl, PTh, PTl, QK, nullptr, nullptr, nullptr, nullptr,
        DIM, 512, (size_t)HW * DIM, 0, (size_t)HW * 512, 0);

    k1b_normalize<<<BATCH * HW, 256>>>();

    // k2: E[n][m] = exp(Qn . Km) + row partial sums  (M=N=4096, K=256)
    gemm_bf16<<<dim3(HW / 128, HW / 128, BATCH), 256, 3 * STGB>>>(
        Qh, Ql, Kh, Kl, nullptr, Eh, El, Part, nullptr,
        IDIM, HW, (size_t)HW * IDIM, (size_t)HW * IDIM, (size_t)HW * HW, 3);

    k3b_inv<<<HW * BATCH / 8, 256>>>();

    // k4: M[n][c] = (sum_m E[n][m] * F[c][m]) * inv[n]  (M=4096, N=512, K=4096)
    gemm_bf16<<<dim3(DIM / 128, HW / 128, BATCH), 256, 3 * STGB>>>(
        Eh, El, Fh, Fl, nullptr, Mh, Ml, nullptr, Inv,
        HW, DIM, (size_t)HW * HW, (size_t)DIM * HW, (size_t)HW * DIM, 4);

    // k5: out[d][n] = relu(Wt[d][:] . M[n][:])   (M=512, N=4096, K=512)
    gemm_bf16<<<dim3(HW / 128, DIM / 128, BATCH), 256, 3 * STGB>>>(
        Wth, Wtl, Mh, Ml, out, nullptr, nullptr, nullptr, nullptr,
        DIM, HW, 0, (size_t)HW * DIM, (size_t)DIM * HW, 1);
}

// round 10
// speedup vs baseline: 1.7143x; 1.6350x over previous
#include <cuda_runtime.h>
#include <cuda_fp16.h>
#include <cstdint>
#include <math.h>

#define BATCH 8
#define DIM   512
#define HW    4096
#define IDIM  256

typedef __half fp16;

// ---------------- device scratch (static) ----------------
__device__ float g_QK[(size_t)BATCH * HW * 512];     // [n][0:256]=phi, [256:512]=theta (fp32)
__device__ fp16  g_Eh[(size_t)BATCH * HW * HW];      // exp(scores), single fp16 plane
__device__ float g_part[(size_t)BATCH * HW * 32];    // per-CTA row partial sums
__device__ float g_inv[(size_t)BATCH * HW];          // 1 / rowsum
__device__ fp16  g_Fth[(size_t)BATCH * HW * DIM];    // F^T [b][n][c], 1 plane
__device__ fp16  g_Fh[(size_t)BATCH * DIM * HW];     // F [b][c][m], 2 planes
__device__ fp16  g_Fl[(size_t)BATCH * DIM * HW];
__device__ fp16  g_Qh[(size_t)BATCH * HW * IDIM];    // normalized phi, 1 plane
__device__ fp16  g_Kh[(size_t)BATCH * HW * IDIM];    // normalized theta, 1 plane
__device__ fp16  g_Mh[(size_t)BATCH * HW * DIM];     // attn out [b][n][c], 2 planes
__device__ fp16  g_Ml[(size_t)BATCH * HW * DIM];
__device__ fp16  g_Wth[(size_t)DIM * DIM];           // W^T [d][c], 2 planes
__device__ fp16  g_Wtl[(size_t)DIM * DIM];
__device__ fp16  g_PTh[(size_t)2 * IDIM * DIM];      // stacked [phi_w; theta_w], 1 plane

// ---------------- helpers ----------------
__device__ __forceinline__ uint32_t smem_u32(const void* p) {
    uint32_t a;
    asm("{ .reg .u64 t; cvta.to.shared.u64 t, %1; cvt.u32.u64 %0, t; }" : "=r"(a) : "l"(p));
    return a;
}
__device__ __forceinline__ void cp16(uint32_t d, const void* s) {
    asm volatile("cp.async.cg.shared.global [%0], [%1], 16;" :: "r"(d), "l"(s));
}
__device__ __forceinline__ void split2(float x, fp16& h, fp16& l) {
    h = __float2half_rn(x);
    l = __float2half_rn(x - __half2float(h));
}

#define LDSM4(R, addr)                                                           \
    asm volatile("ldmatrix.sync.aligned.m8n8.x4.shared.b16 {%0,%1,%2,%3}, [%4];" \
        : "=r"((R)[0]), "=r"((R)[1]), "=r"((R)[2]), "=r"((R)[3]) : "r"(addr))

#define MMA_FP16(c, a, b0, b1)                                                   \
    asm volatile(                                                                \
        "mma.sync.aligned.m16n8k16.row.col.f32.f16.f16.f32 "                     \
        "{%0,%1,%2,%3}, {%4,%5,%6,%7}, {%8,%9}, {%0,%1,%2,%3};"                  \
        : "+f"((c)[0]), "+f"((c)[1]), "+f"((c)[2]), "+f"((c)[3])                 \
        : "r"((a)[0]), "r"((a)[1]), "r"((a)[2]), "r"((a)[3]),                    \
          "r"((b0)), "r"((b1)))

// BK=32: rows are 64B (4 x 16B granules). granule q of row r stored at q ^ ((r>>1)&3).
// Plane layout (per stage): A planes at p*8192, B planes at (NA+p)*8192.
__device__ __forceinline__ void fill_pl(uint32_t dbase, const fp16* src, int Kdim, int tid) {
    #pragma unroll
    for (int t = 0; t < 2; t++) {
        int idx = tid + t * 256;
        int row = idx >> 2, q = idx & 3;
        cp16(dbase + row * 64 + ((q ^ ((row >> 1) & 3)) << 4),
             src + (size_t)row * Kdim + q * 8);
    }
}

// ================= fp16 multi-plane NT GEMM via mma.sync + ldmatrix =================
// C[m][n] = sum_k A[m][k]*B[n][k].  NA/NB = planes per operand (1 or 2), lo*lo dropped.
// CTA 128x128, 8 warps (2x4) of 64x32, BK=32, cp.async 3-stage pipeline.
// MODE 0: fp32 store   1: relu fp32 store
// MODE 3: exp() + 1-plane fp16 store + row partial sums (k2)
// MODE 4: row scale by Inv + 2-plane fp16 store (k4)
template<int NA, int NB, int MODE>
__global__ void __launch_bounds__(256) gemm_fp16(
    const fp16* __restrict__ Ah, const fp16* __restrict__ Al,
    const fp16* __restrict__ Bh, const fp16* __restrict__ Bl,
    float* __restrict__ C, fp16* __restrict__ Ch, fp16* __restrict__ Cl,
    float* __restrict__ Part, const float* __restrict__ Inv,
    int Kdim, int Ncols, size_t sA, size_t sB, size_t sC)
{
    constexpr int SPS = (NA + NB) * 8192;     // stage bytes
    extern __shared__ char smem[];
    const int tid  = threadIdx.x;
    const int lane = tid & 31, wid = tid >> 5;
    const int g = lane >> 2, tg = lane & 3;
    const int wm = wid >> 2, wn = wid & 3;
    const uint32_t sb = smem_u32(smem);

    const size_t aoff = blockIdx.z * sA + (size_t)blockIdx.y * 128 * Kdim;
    const size_t boff = blockIdx.z * sB + (size_t)blockIdx.x * 128 * Kdim;
    const fp16* pA[2] = { Ah + aoff, (NA == 2) ? Al + aoff : nullptr };
    const fp16* pB[2] = { Bh + boff, (NB == 2) ? Bl + boff : nullptr };

    float acc[4][4][4];
    #pragma unroll
    for (int i = 0; i < 4; i++)
        #pragma unroll
        for (int j = 0; j < 4; j++)
            #pragma unroll
            for (int e = 0; e < 4; e++) acc[i][j][e] = 0.f;

    const int NC = Kdim >> 5;
    const int rb = lane & 15, gs = lane >> 4;
    const int swz = (rb >> 1) & 3;

    // prefetch stages 0,1
    #pragma unroll
    for (int p = 0; p < NA; p++) fill_pl(sb + p * 8192, pA[p], Kdim, tid);
    #pragma unroll
    for (int p = 0; p < NB; p++) fill_pl(sb + (NA + p) * 8192, pB[p], Kdim, tid);
    asm volatile("cp.async.commit_group;");
    if (NC > 1) {
        #pragma unroll
        for (int p = 0; p < NA; p++) fill_pl(sb + SPS + p * 8192, pA[p] + 32, Kdim, tid);
        #pragma unroll
        for (int p = 0; p < NB; p++) fill_pl(sb + SPS + (NA + p) * 8192, pB[p] + 32, Kdim, tid);
        asm volatile("cp.async.commit_group;");
    }

    int st = 0;
    for (int c = 0; c < NC; c++) {
        if (c + 2 < NC) {
            uint32_t nb = sb + ((c + 2) % 3) * SPS;
            int ko = (c + 2) * 32;
            #pragma unroll
            for (int p = 0; p < NA; p++) fill_pl(nb + p * 8192, pA[p] + ko, Kdim, tid);
            #pragma unroll
            for (int p = 0; p < NB; p++) fill_pl(nb + (NA + p) * 8192, pB[p] + ko, Kdim, tid);
            asm volatile("cp.async.commit_group;");
            asm volatile("cp.async.wait_group 2;");
        } else if (c + 2 == NC) {
            asm volatile("cp.async.wait_group 1;");
        } else {
            asm volatile("cp.async.wait_group 0;");
        }
        __syncthreads();

        uint32_t bb = sb + st * SPS;
        #pragma unroll
        for (int s = 0; s < 2; s++) {
            const int gp = (((2 * s + gs) ^ swz) << 4);
            uint32_t af[2][4][4], bf[2][2][4];
            #pragma unroll
            for (int p = 0; p < NA; p++)
                #pragma unroll
                for (int i = 0; i < 4; i++) {
                    uint32_t ra = bb + p * 8192 + (uint32_t)(wm * 64 + i * 16 + rb) * 64 + gp;
                    LDSM4(af[p][i], ra);
                }
            #pragma unroll
            for (int p = 0; p < NB; p++)
                #pragma unroll
                for (int t = 0; t < 2; t++) {
                    uint32_t rba = bb + (NA + p) * 8192 + (uint32_t)(wn * 32 + t * 16 + rb) * 64 + gp;
                    LDSM4(bf[p][t], rba);
                }
            #pragma unroll
            for (int i = 0; i < 4; i++)
                #pragma unroll
                for (int j = 0; j < 4; j++) {
                    const int t = j >> 1, u = j & 1;
                    MMA_FP16(acc[i][j], af[0][i], bf[0][t][u], bf[0][t][u + 2]);
                    if (NB == 2)
                        MMA_FP16(acc[i][j], af[0][i], bf[1][t][u], bf[1][t][u + 2]);
                    if (NA == 2)
                        MMA_FP16(acc[i][j], af[1][i], bf[0][t][u], bf[0][t][u + 2]);
                }
        }
        __syncthreads();
        if (++st == 3) st = 0;
    }

    // ---------------- epilogue ----------------
    const int row0 = blockIdx.y * 128 + wm * 64;
    const int col0 = blockIdx.x * 128 + wn * 3 * 0 + wn * 32;
    const int bz = blockIdx.z;

    if (MODE == 3) {
        float* spart = (float*)smem;   // [128][4]
        float rsum[4][2];
        #pragma unroll
        for (int i = 0; i < 4; i++) { rsum[i][0] = 0.f; rsum[i][1] = 0.f; }
        #pragma unroll
        for (int i = 0; i < 4; i++) {
            int r0 = row0 + i * 16 + g;
            #pragma unroll
            for (int j = 0; j < 4; j++) {
                int cc = col0 + j * 8 + tg * 2;
                float e0 = __expf(acc[i][j][0]);
                float e1 = __expf(acc[i][j][1]);
                float e2 = __expf(acc[i][j][2]);
                float e3 = __expf(acc[i][j][3]);
                rsum[i][0] += e0 + e1;
                rsum[i][1] += e2 + e3;
                size_t o0 = bz * sC + (size_t)r0 * Ncols + cc;
                size_t o1 = o0 + 8 * (size_t)Ncols;
                __half2 p0; p0.x = __float2half_rn(e0); p0.y = __float2half_rn(e1);
                __half2 p1; p1.x = __float2half_rn(e2); p1.y = __float2half_rn(e3);
                *reinterpret_cast<__half2*>(Ch + o0) = p0;
                *reinterpret_cast<__half2*>(Ch + o1) = p1;
            }
        }
        #pragma unroll
        for (int i = 0; i < 4; i++) {
            #pragma unroll
            for (int h = 0; h < 2; h++) {
                float v = rsum[i][h];
                v += __shfl_xor_sync(0xffffffffu, v, 1);
                v += __shfl_xor_sync(0xffffffffu, v, 2);
                if (tg == 0)
                    spart[(wm * 64 + i * 16 + g + h * 8) * 4 + wn] = v;
            }
        }
        __syncthreads();
        if (tid < 128) {
            float4 p = *reinterpret_cast<float4*>(spart + tid * 4);
            Part[((size_t)bz * HW + blockIdx.y * 128 + tid) * 32 + blockIdx.x] =
                p.x + p.y + p.z + p.w;
        }
        return;
    }

    #pragma unroll
    for (int i = 0; i < 4; i++) {
        int r0 = row0 + i * 16 + g;
        float inv0 = 1.f, inv1 = 1.f;
        if (MODE == 4) {
            inv0 = Inv[(size_t)bz * HW + r0];
            inv1 = Inv[(size_t)bz * HW + r0 + 8];
        }
        #pragma unroll
        for (int j = 0; j < 4; j++) {
            int cc = col0 + j * 8 + tg * 2;
            if (MODE == 4) {
                size_t o0 = bz * sC + (size_t)r0 * Ncols + cc;
                size_t o1 = o0 + 8 * (size_t)Ncols;
                fp16 h0, l0, h1, l1;
                __half2 hh, ll;
                split2(acc[i][j][0] * inv0, h0, l0);
                split2(acc[i][j][1] * inv0, h1, l1);
                hh.x = h0; hh.y = h1; ll.x = l0; ll.y = l1;
                *reinterpret_cast<__half2*>(Ch + o0) = hh;
                *reinterpret_cast<__half2*>(Cl + o0) = ll;
                split2(acc[i][j][2] * inv1, h0, l0);
                split2(acc[i][j][3] * inv1, h1, l1);
                hh.x = h0; hh.y = h1; ll.x = l0; ll.y = l1;
                *reinterpret_cast<__half2*>(Ch + o1) = hh;
                *reinterpret_cast<__half2*>(Cl + o1) = ll;
            } else {
                float* b0 = C + bz * sC + (size_t)r0 * Ncols + cc;
                float* b1 = b0 + 8 * (size_t)Ncols;
                float2 v0, v1;
                v0.x = acc[i][j][0]; v0.y = acc[i][j][1];
                v1.x = acc[i][j][2]; v1.y = acc[i][j][3];
                if (MODE == 1) {
                    v0.x = fmaxf(v0.x, 0.f); v0.y = fmaxf(v0.y, 0.f);
                    v1.x = fmaxf(v1.x, 0.f); v1.y = fmaxf(v1.y, 0.f);
                }
                *reinterpret_cast<float2*>(b0) = v0;
                *reinterpret_cast<float2*>(b1) = v1;
            }
        }
    }
}

// ---------------- inv rowsum ----------------
__global__ void __launch_bounds__(256) k3b_inv() {
    int wid = threadIdx.x >> 5, lane = threadIdx.x & 31;
    size_t rr = (size_t)blockIdx.x * 8 + wid;
    float v = g_part[rr * 32 + lane];
    #pragma unroll
    for (int o = 16; o > 0; o >>= 1) v += __shfl_xor_sync(0xffffffffu, v, o);
    if (lane == 0) g_inv[rr] = 1.0f / v;
}

// ---------------- transpose, 1-plane fp16 ----------------
__global__ void __launch_bounds__(256) trans1(const float* __restrict__ in,
                                              fp16* __restrict__ oh, int R, int C) {
    __shared__ float t[32][33];
    int b = blockIdx.z;
    const float* ib = in + (size_t)b * R * C;
    size_t ob = (size_t)b * R * C;
    int c0 = blockIdx.x * 32, r0 = blockIdx.y * 32;
    int x = threadIdx.x, y = threadIdx.y;
    #pragma unroll
    for (int i = 0; i < 32; i += 8)
        t[y + i][x] = ib[(size_t)(r0 + y + i) * C + c0 + x];
    __syncthreads();
    #pragma unroll
    for (int i = 0; i < 32; i += 8)
        oh[ob + (size_t)(c0 + y + i) * R + r0 + x] = __float2half_rn(t[x][y + i]);
}

// ---------------- transpose, 2-plane fp16 ----------------
__global__ void __launch_bounds__(256) trans2(const float* __restrict__ in,
                                              fp16* __restrict__ oh, fp16* __restrict__ ol,
                                              int R, int C) {
    __shared__ float t[32][33];
    int b = blockIdx.z;
    const float* ib = in + (size_t)b * R * C;
    size_t ob = (size_t)b * R * C;
    int c0 = blockIdx.x * 32, r0 = blockIdx.y * 32;
    int x = threadIdx.x, y = threadIdx.y;
    #pragma unroll
    for (int i = 0; i < 32; i += 8)
        t[y + i][x] = ib[(size_t)(r0 + y + i) * C + c0 + x];
    __syncthreads();
    #pragma unroll
    for (int i = 0; i < 32; i += 8) {
        fp16 h, l; split2(t[x][y + i], h, l);
        size_t o = ob + (size_t)(c0 + y + i) * R + r0 + x;
        oh[o] = h; ol[o] = l;
    }
}

// ---------------- elementwise fp16 conversions ----------------
__global__ void __launch_bounds__(256) conv1(const float* __restrict__ in,
                                             fp16* __restrict__ oh) {
    size_t i0 = ((size_t)blockIdx.x * 256 + threadIdx.x) * 4;
    float4 v = *reinterpret_cast<const float4*>(in + i0);
    __half2 a, b;
    a.x = __float2half_rn(v.x); a.y = __float2half_rn(v.y);
    b.x = __float2half_rn(v.z); b.y = __float2half_rn(v.w);
    *reinterpret_cast<__half2*>(oh + i0)     = a;
    *reinterpret_cast<__half2*>(oh + i0 + 2) = b;
}
__global__ void __launch_bounds__(256) conv2(const float* __restrict__ in,
                                             fp16* __restrict__ oh, fp16* __restrict__ ol) {
    size_t i0 = ((size_t)blockIdx.x * 256 + threadIdx.x) * 4;
    float4 v = *reinterpret_cast<const float4*>(in + i0);
    fp16 h0, l0, h1, l1;
    __half2 hh, ll;
    split2(v.x, h0, l0); split2(v.y, h1, l1);
    hh.x = h0; hh.y = h1; ll.x = l0; ll.y = l1;
    *reinterpret_cast<__half2*>(oh + i0) = hh;
    *reinterpret_cast<__half2*>(ol + i0) = ll;
    split2(v.z, h0, l0); split2(v.w, h1, l1);
    hh.x = h0; hh.y = h1; ll.x = l0; ll.y = l1;
    *reinterpret_cast<__half2*>(oh + i0 + 2) = hh;
    *reinterpret_cast<__half2*>(ol + i0 + 2) = ll;
}

// ---------------- normalize phi/theta rows -> fp16 planes ----------------
__global__ void __launch_bounds__(256) k1b_normalize() {
    size_t row = blockIdx.x;
    const float* qk = g_QK + row * 512;
    int t = threadIdx.x;
    float qv = qk[t], kv = qk[256 + t];
    float sq = qv * qv, sk = kv * kv;
    #pragma unroll
    for (int o = 16; o > 0; o >>= 1) {
        sq += __shfl_xor_sync(0xffffffffu, sq, o);
        sk += __shfl_xor_sync(0xffffffffu, sk, o);
    }
    __shared__ float sh[16];
    int w = t >> 5;
    if ((t & 31) == 0) { sh[w] = sq; sh[8 + w] = sk; }
    __syncthreads();
    float tq = 0.f, tk = 0.f;
    #pragma unroll
    for (int i = 0; i < 8; i++) { tq += sh[i]; tk += sh[8 + i]; }
    size_t o = row * IDIM + t;
    g_Qh[o] = __float2half_rn(qv / sqrtf(tq));
    g_Kh[o] = __float2half_rn(kv / sqrtf(tk));
}

// ---------------- launch ----------------
extern "C" void kernel_launch(void* const* d_in, const int* in_sizes, int n_in,
                              void* d_out, int out_size) {
    const float* feat    = (const float*)d_in[0];   // [8, 512, 64, 64]
    const float* phi_w   = (const float*)d_in[1];   // [256, 512]
    const float* theta_w = (const float*)d_in[2];   // [256, 512]
    const float* weight  = (const float*)d_in[3];   // [512, 512]
    float* out = (float*)d_out;                     // [8, 512, 64, 64]

    cudaFuncSetAttribute(gemm_fp16<1,1,0>, cudaFuncAttributeMaxDynamicSharedMemorySize, 3 * 2 * 8192);
    cudaFuncSetAttribute(gemm_fp16<1,1,3>, cudaFuncAttributeMaxDynamicSharedMemorySize, 3 * 2 * 8192);
    cudaFuncSetAttribute(gemm_fp16<1,2,4>, cudaFuncAttributeMaxDynamicSharedMemorySize, 3 * 3 * 8192);
    cudaFuncSetAttribute(gemm_fp16<2,2,1>, cudaFuncAttributeMaxDynamicSharedMemorySize, 3 * 4 * 8192);

    float *QK, *Part, *Inv;
    fp16 *Eh, *Fth, *Fh, *Fl, *Qh, *Kh, *Mh, *Ml, *Wth, *Wtl, *PTh;
    cudaGetSymbolAddress((void**)&QK,   g_QK);
    cudaGetSymbolAddress((void**)&Part, g_part);
    cudaGetSymbolAddress((void**)&Inv,  g_inv);
    cudaGetSymbolAddress((void**)&Eh,   g_Eh);
    cudaGetSymbolAddress((void**)&Fth,  g_Fth);
    cudaGetSymbolAddress((void**)&Fh,   g_Fh);
    cudaGetSymbolAddress((void**)&Fl,   g_Fl);
    cudaGetSymbolAddress((void**)&Qh,   g_Qh);
    cudaGetSymbolAddress((void**)&Kh,   g_Kh);
    cudaGetSymbolAddress((void**)&Mh,   g_Mh);
    cudaGetSymbolAddress((void**)&Ml,   g_Ml);
    cudaGetSymbolAddress((void**)&Wth,  g_Wth);
    cudaGetSymbolAddress((void**)&Wtl,  g_Wtl);
    cudaGetSymbolAddress((void**)&PTh,  g_PTh);

    // prep
    trans1<<<dim3(HW / 32, DIM / 32, BATCH), dim3(32, 8)>>>(feat, Fth, DIM, HW);
    trans2<<<dim3(DIM / 32, DIM / 32, 1), dim3(32, 8)>>>(weight, Wth, Wtl, DIM, DIM);
    conv2<<<(BATCH * DIM * HW) / 1024, 256>>>(feat, Fh, Fl);
    conv1<<<(IDIM * DIM) / 1024, 256>>>(phi_w, PTh);
    conv1<<<(IDIM * DIM) / 1024, 256>>>(theta_w, PTh + (size_t)IDIM * DIM);

    // k1 (merged): QK[n][j] = Ft[n][:] . [phi_w;theta_w][j][:]  (M=4096, N=512, K=512)
    gemm_fp16<1,1,0><<<dim3(512 / 128, HW / 128, BATCH), 256, 3 * 2 * 8192>>>(
        Fth, nullptr, PTh, nullptr, QK, nullptr, nullptr, nullptr, nullptr,
        DIM, 512, (size_t)HW * DIM, 0, (size_t)HW * 512);

    k1b_normalize<<<BATCH * HW, 256>>>();

    // k2: E[n][m] = exp(Qn . Km) + row partial sums  (M=N=4096, K=256)
    gemm_fp16<1,1,3><<<dim3(HW / 128, HW / 128, BATCH), 256, 3 * 2 * 8192>>>(
        Qh, nullptr, Kh, nullptr, nullptr, Eh, nullptr, Part, nullptr,
        IDIM, HW, (size_t)HW * IDIM, (size_t)HW * IDIM, (size_t)HW * HW);

    k3b_inv<<<HW * BATCH / 8, 256>>>();

    // k4: M[n][c] = (sum_m E[n][m] * F[c][m]) * inv[n]  (M=4096, N=512, K=4096)
    gemm_fp16<1,2,4><<<dim3(DIM / 128, HW / 128, BATCH), 256, 3 * 3 * 8192>>>(
        Eh, nullptr, Fh, Fl, nullptr, Mh, Ml, nullptr, Inv,
        HW, DIM, (size_t)HW * HW, (size_t)DIM * HW, (size_t)HW * DIM);

    // k5: out[d][n] = relu(Wt[d][:] . M[n][:])   (M=512, N=4096, K=512)
    gemm_fp16<2,2,1><<<dim3(HW / 128, DIM / 128, BATCH), 256, 3 * 4 * 8192>>>(
        Wth, Wtl, Mh, Ml, out, nullptr, nullptr, nullptr, nullptr,
        DIM, HW, 0, (size_t)HW * DIM, (size_t)DIM * HW);
}

// round 12
// speedup vs baseline: 2.3581x; 1.3755x over previous
#include <cuda_runtime.h>
#include <cuda_fp16.h>
#include <cstdint>
#include <math.h>

#define BATCH 8
#define DIM   512
#define HW    4096
#define IDIM  256

typedef __half fp16;

// ---------------- device scratch (static) ----------------
__device__ float g_QK[(size_t)BATCH * HW * 512];     // [n][0:256]=phi, [256:512]=theta (fp32)
__device__ fp16  g_Eh[(size_t)BATCH * HW * HW];      // exp(scores), single fp16 plane
__device__ float g_part[(size_t)BATCH * HW * 32];    // per-CTA row partial sums
__device__ float g_inv[(size_t)BATCH * HW];          // 1 / rowsum
__device__ fp16  g_Fth[(size_t)BATCH * HW * DIM];    // F^T [b][n][c], 1 plane
__device__ fp16  g_Fh[(size_t)BATCH * DIM * HW];     // F [b][c][m], 1 plane
__device__ fp16  g_Qh[(size_t)BATCH * HW * IDIM];    // normalized phi, 1 plane
__device__ fp16  g_Kh[(size_t)BATCH * HW * IDIM];    // normalized theta, 1 plane
__device__ fp16  g_Mh[(size_t)BATCH * HW * DIM];     // attn out [b][n][c], 1 plane
__device__ fp16  g_Wth[(size_t)DIM * DIM];           // W^T [d][c], 2 planes
__device__ fp16  g_Wtl[(size_t)DIM * DIM];
__device__ fp16  g_PTh[(size_t)2 * IDIM * DIM];      // stacked [phi_w; theta_w], 1 plane

// ---------------- helpers ----------------
__device__ __forceinline__ uint32_t smem_u32(const void* p) {
    uint32_t a;
    asm("{ .reg .u64 t; cvta.to.shared.u64 t, %1; cvt.u32.u64 %0, t; }" : "=r"(a) : "l"(p));
    return a;
}
__device__ __forceinline__ void cp16(uint32_t d, const void* s) {
    asm volatile("cp.async.cg.shared.global [%0], [%1], 16;" :: "r"(d), "l"(s));
}
__device__ __forceinline__ void split2(float x, fp16& h, fp16& l) {
    h = __float2half_rn(x);
    l = __float2half_rn(x - __half2float(h));
}

#define LDSM4(R, addr)                                                           \
    asm volatile("ldmatrix.sync.aligned.m8n8.x4.shared.b16 {%0,%1,%2,%3}, [%4];" \
        : "=r"((R)[0]), "=r"((R)[1]), "=r"((R)[2]), "=r"((R)[3]) : "r"(addr))

#define MMA_FP16(c, a, b0, b1)                                                   \
    asm volatile(                                                                \
        "mma.sync.aligned.m16n8k16.row.col.f32.f16.f16.f32 "                     \
        "{%0,%1,%2,%3}, {%4,%5,%6,%7}, {%8,%9}, {%0,%1,%2,%3};"                  \
        : "+f"((c)[0]), "+f"((c)[1]), "+f"((c)[2]), "+f"((c)[3])                 \
        : "r"((a)[0]), "r"((a)[1]), "r"((a)[2]), "r"((a)[3]),                    \
          "r"((b0)), "r"((b1)))

// BK=32: rows are 64B (4 x 16B granules). granule q of row r stored at q ^ ((r>>1)&3).
// Plane layout (per stage): A planes at p*8192, B planes at (NA+p)*8192.
__device__ __forceinline__ void fill_pl(uint32_t dbase, const fp16* src, int Kdim, int tid) {
    #pragma unroll
    for (int t = 0; t < 2; t++) {
        int idx = tid + t * 256;
        int row = idx >> 2, q = idx & 3;
        cp16(dbase + row * 64 + ((q ^ ((row >> 1) & 3)) << 4),
             src + (size_t)row * Kdim + q * 8);
    }
}

// ================= fp16 multi-plane NT GEMM via mma.sync + ldmatrix =================
// C[m][n] = sum_k A[m][k]*B[n][k].  NA/NB = planes per operand (1 or 2), lo*lo dropped.
// CTA 128x128, 8 warps (2x4) of 64x32, BK=32, cp.async 3-stage pipeline.
// MODE 0: fp32 store   1: relu fp32 store
// MODE 3: exp() + 1-plane fp16 store + row partial sums (k2)
// MODE 4: row scale by Inv + 1-plane fp16 store (k4)
template<int NA, int NB, int MODE>
__global__ void __launch_bounds__(256) gemm_fp16(
    const fp16* __restrict__ Ah, const fp16* __restrict__ Al,
    const fp16* __restrict__ Bh, const fp16* __restrict__ Bl,
    float* __restrict__ C, fp16* __restrict__ Ch,
    float* __restrict__ Part, const float* __restrict__ Inv,
    int Kdim, int Ncols, size_t sA, size_t sB, size_t sC)
{
    constexpr int SPS = (NA + NB) * 8192;     // stage bytes
    extern __shared__ char smem[];
    const int tid  = threadIdx.x;
    const int lane = tid & 31, wid = tid >> 5;
    const int g = lane >> 2, tg = lane & 3;
    const int wm = wid >> 2, wn = wid & 3;
    const uint32_t sb = smem_u32(smem);

    const size_t aoff = blockIdx.z * sA + (size_t)blockIdx.y * 128 * Kdim;
    const size_t boff = blockIdx.z * sB + (size_t)blockIdx.x * 128 * Kdim;
    const fp16* pA[2] = { Ah + aoff, (NA == 2) ? Al + aoff : nullptr };
    const fp16* pB[2] = { Bh + boff, (NB == 2) ? Bl + boff : nullptr };

    float acc[4][4][4];
    #pragma unroll
    for (int i = 0; i < 4; i++)
        #pragma unroll
        for (int j = 0; j < 4; j++)
            #pragma unroll
            for (int e = 0; e < 4; e++) acc[i][j][e] = 0.f;

    const int NC = Kdim >> 5;
    const int rb = lane & 15, gs = lane >> 4;
    const int swz = (rb >> 1) & 3;

    // prefetch stages 0,1
    #pragma unroll
    for (int p = 0; p < NA; p++) fill_pl(sb + p * 8192, pA[p], Kdim, tid);
    #pragma unroll
    for (int p = 0; p < NB; p++) fill_pl(sb + (NA + p) * 8192, pB[p], Kdim, tid);
    asm volatile("cp.async.commit_group;");
    if (NC > 1) {
        #pragma unroll
        for (int p = 0; p < NA; p++) fill_pl(sb + SPS + p * 8192, pA[p] + 32, Kdim, tid);
        #pragma unroll
        for (int p = 0; p < NB; p++) fill_pl(sb + SPS + (NA + p) * 8192, pB[p] + 32, Kdim, tid);
        asm volatile("cp.async.commit_group;");
    }

    int st = 0;
    for (int c = 0; c < NC; c++) {
        if (c + 2 < NC) {
            uint32_t nb = sb + ((c + 2) % 3) * SPS;
            int ko = (c + 2) * 32;
            #pragma unroll
            for (int p = 0; p < NA; p++) fill_pl(nb + p * 8192, pA[p] + ko, Kdim, tid);
            #pragma unroll
            for (int p = 0; p < NB; p++) fill_pl(nb + (NA + p) * 8192, pB[p] + ko, Kdim, tid);
            asm volatile("cp.async.commit_group;");
            asm volatile("cp.async.wait_group 2;");
        } else if (c + 2 == NC) {
            asm volatile("cp.async.wait_group 1;");
        } else {
            asm volatile("cp.async.wait_group 0;");
        }
        __syncthreads();

        uint32_t bb = sb + st * SPS;
        #pragma unroll
        for (int s = 0; s < 2; s++) {
            const int gp = (((2 * s + gs) ^ swz) << 4);
            uint32_t af[2][4][4], bf[2][2][4];
            #pragma unroll
            for (int p = 0; p < NA; p++)
                #pragma unroll
                for (int i = 0; i < 4; i++) {
                    uint32_t ra = bb + p * 8192 + (uint32_t)(wm * 64 + i * 16 + rb) * 64 + gp;
                    LDSM4(af[p][i], ra);
                }
            #pragma unroll
            for (int p = 0; p < NB; p++)
                #pragma unroll
                for (int t = 0; t < 2; t++) {
                    uint32_t rba = bb + (NA + p) * 8192 + (uint32_t)(wn * 32 + t * 16 + rb) * 64 + gp;
                    LDSM4(bf[p][t], rba);
                }
            #pragma unroll
            for (int i = 0; i < 4; i++)
                #pragma unroll
                for (int j = 0; j < 4; j++) {
                    const int t = j >> 1, u = j & 1;
                    MMA_FP16(acc[i][j], af[0][i], bf[0][t][u], bf[0][t][u + 2]);
                    if (NB == 2)
                        MMA_FP16(acc[i][j], af[0][i], bf[1][t][u], bf[1][t][u + 2]);
                    if (NA == 2)
                        MMA_FP16(acc[i][j], af[1][i], bf[0][t][u], bf[0][t][u + 2]);
                }
        }
        __syncthreads();
        if (++st == 3) st = 0;
    }

    // ---------------- epilogue ----------------
    const int row0 = blockIdx.y * 128 + wm * 64;
    const int col0 = blockIdx.x * 128 + wn * 32;
    const int bz = blockIdx.z;

    if (MODE == 3) {
        float* spart = (float*)smem;   // [128][4]
        float rsum[4][2];
        #pragma unroll
        for (int i = 0; i < 4; i++) { rsum[i][0] = 0.f; rsum[i][1] = 0.f; }
        #pragma unroll
        for (int i = 0; i < 4; i++) {
            int r0 = row0 + i * 16 + g;
            #pragma unroll
            for (int j = 0; j < 4; j++) {
                int cc = col0 + j * 8 + tg * 2;
                float e0 = __expf(acc[i][j][0]);
                float e1 = __expf(acc[i][j][1]);
                float e2 = __expf(acc[i][j][2]);
                float e3 = __expf(acc[i][j][3]);
                rsum[i][0] += e0 + e1;
                rsum[i][1] += e2 + e3;
                size_t o0 = bz * sC + (size_t)r0 * Ncols + cc;
                size_t o1 = o0 + 8 * (size_t)Ncols;
                __half2 p0; p0.x = __float2half_rn(e0); p0.y = __float2half_rn(e1);
                __half2 p1; p1.x = __float2half_rn(e2); p1.y = __float2half_rn(e3);
                *reinterpret_cast<__half2*>(Ch + o0) = p0;
                *reinterpret_cast<__half2*>(Ch + o1) = p1;
            }
        }
        #pragma unroll
        for (int i = 0; i < 4; i++) {
            #pragma unroll
            for (int h = 0; h < 2; h++) {
                float v = rsum[i][h];
                v += __shfl_xor_sync(0xffffffffu, v, 1);
                v += __shfl_xor_sync(0xffffffffu, v, 2);
                if (tg == 0)
                    spart[(wm * 64 + i * 16 + g + h * 8) * 4 + wn] = v;
            }
        }
        __syncthreads();
        if (tid < 128) {
            float4 p = *reinterpret_cast<float4*>(spart + tid * 4);
            Part[((size_t)bz * HW + blockIdx.y * 128 + tid) * 32 + blockIdx.x] =
                p.x + p.y + p.z + p.w;
        }
        return;
    }

    #pragma unroll
    for (int i = 0; i < 4; i++) {
        int r0 = row0 + i * 16 + g;
        float inv0 = 1.f, inv1 = 1.f;
        if (MODE == 4) {
            inv0 = Inv[(size_t)bz * HW + r0];
            inv1 = Inv[(size_t)bz * HW + r0 + 8];
        }
        #pragma unroll
        for (int j = 0; j < 4; j++) {
            int cc = col0 + j * 8 + tg * 2;
            if (MODE == 4) {
                size_t o0 = bz * sC + (size_t)r0 * Ncols + cc;
                size_t o1 = o0 + 8 * (size_t)Ncols;
                __half2 p0, p1;
                p0.x = __float2half_rn(acc[i][j][0] * inv0);
                p0.y = __float2half_rn(acc[i][j][1] * inv0);
                p1.x = __float2half_rn(acc[i][j][2] * inv1);
                p1.y = __float2half_rn(acc[i][j][3] * inv1);
                *reinterpret_cast<__half2*>(Ch + o0) = p0;
                *reinterpret_cast<__half2*>(Ch + o1) = p1;
            } else {
                float* b0 = C + bz * sC + (size_t)r0 * Ncols + cc;
                float* b1 = b0 + 8 * (size_t)Ncols;
                float2 v0, v1;
                v0.x = acc[i][j][0]; v0.y = acc[i][j][1];
                v1.x = acc[i][j][2]; v1.y = acc[i][j][3];
                if (MODE == 1) {
                    v0.x = fmaxf(v0.x, 0.f); v0.y = fmaxf(v0.y, 0.f);
                    v1.x = fmaxf(v1.x, 0.f); v1.y = fmaxf(v1.y, 0.f);
                }
                *reinterpret_cast<float2*>(b0) = v0;
                *reinterpret_cast<float2*>(b1) = v1;
            }
        }
    }
}

// ---------------- inv rowsum ----------------
__global__ void __launch_bounds__(256) k3b_inv() {
    int wid = threadIdx.x >> 5, lane = threadIdx.x & 31;
    size_t rr = (size_t)blockIdx.x * 8 + wid;
    float v = g_part[rr * 32 + lane];
    #pragma unroll
    for (int o = 16; o > 0; o >>= 1) v += __shfl_xor_sync(0xffffffffu, v, o);
    if (lane == 0) g_inv[rr] = 1.0f / v;
}

// ---------------- transpose, 1-plane fp16 ----------------
__global__ void __launch_bounds__(256) trans1(const float* __restrict__ in,
                                              fp16* __restrict__ oh, int R, int C) {
    __shared__ float t[32][33];
    int b = blockIdx.z;
    const float* ib = in + (size_t)b * R * C;
    size_t ob = (size_t)b * R * C;
    int c0 = blockIdx.x * 32, r0 = blockIdx.y * 32;
    int x = threadIdx.x, y = threadIdx.y;
    #pragma unroll
    for (int i = 0; i < 32; i += 8)
        t[y + i][x] = ib[(size_t)(r0 + y + i) * C + c0 + x];
    __syncthreads();
    #pragma unroll
    for (int i = 0; i < 32; i += 8)
        oh[ob + (size_t)(c0 + y + i) * R + r0 + x] = __float2half_rn(t[x][y + i]);
}

// ---------------- transpose, 2-plane fp16 ----------------
__global__ void __launch_bounds__(256) trans2(const float* __restrict__ in,
                                              fp16* __restrict__ oh, fp16* __restrict__ ol,
                                              int R, int C) {
    __shared__ float t[32][33];
    int b = blockIdx.z;
    const float* ib = in + (size_t)b * R * C;
    size_t ob = (size_t)b * R * C;
    int c0 = blockIdx.x * 32, r0 = blockIdx.y * 32;
    int x = threadIdx.x, y = threadIdx.y;
    #pragma unroll
    for (int i = 0; i < 32; i += 8)
        t[y + i][x] = ib[(size_t)(r0 + y + i) * C + c0 + x];
    __syncthreads();
    #pragma unroll
    for (int i = 0; i < 32; i += 8) {
        fp16 h, l; split2(t[x][y + i], h, l);
        size_t o = ob + (size_t)(c0 + y + i) * R + r0 + x;
        oh[o] = h; ol[o] = l;
    }
}

// ---------------- elementwise fp16 conversion, 1 plane ----------------
__global__ void __launch_bounds__(256) conv1(const float* __restrict__ in,
                                             fp16* __restrict__ oh) {
    size_t i0 = ((size_t)blockIdx.x * 256 + threadIdx.x) * 4;
    float4 v = *reinterpret_cast<const float4*>(in + i0);
    __half2 a, b;
    a.x = __float2half_rn(v.x); a.y = __float2half_rn(v.y);
    b.x = __float2half_rn(v.z); b.y = __float2half_rn(v.w);
    *reinterpret_cast<__half2*>(oh + i0)     = a;
    *reinterpret_cast<__half2*>(oh + i0 + 2) = b;
}

// ---------------- normalize phi/theta rows -> fp16 planes ----------------
__global__ void __launch_bounds__(256) k1b_normalize() {
    size_t row = blockIdx.x;
    const float* qk = g_QK + row * 512;
    int t = threadIdx.x;
    float qv = qk[t], kv = qk[256 + t];
    float sq = qv * qv, sk = kv * kv;
    #pragma unroll
    for (int o = 16; o > 0; o >>= 1) {
        sq += __shfl_xor_sync(0xffffffffu, sq, o);
        sk += __shfl_xor_sync(0xffffffffu, sk, o);
    }
    __shared__ float sh[16];
    int w = t >> 5;
    if ((t & 31) == 0) { sh[w] = sq; sh[8 + w] = sk; }
    __syncthreads();
    float tq = 0.f, tk = 0.f;
    #pragma unroll
    for (int i = 0; i < 8; i++) { tq += sh[i]; tk += sh[8 + i]; }
    size_t o = row * IDIM + t;
    g_Qh[o] = __float2half_rn(qv / sqrtf(tq));
    g_Kh[o] = __float2half_rn(kv / sqrtf(tk));
}

// ---------------- launch ----------------
extern "C" void kernel_launch(void* const* d_in, const int* in_sizes, int n_in,
                              void* d_out, int out_size) {
    const float* feat    = (const float*)d_in[0];   // [8, 512, 64, 64]
    const float* phi_w   = (const float*)d_in[1];   // [256, 512]
    const float* theta_w = (const float*)d_in[2];   // [256, 512]
    const float* weight  = (const float*)d_in[3];   // [512, 512]
    float* out = (float*)d_out;                     // [8, 512, 64, 64]

    cudaFuncSetAttribute(gemm_fp16<1,1,0>, cudaFuncAttributeMaxDynamicSharedMemorySize, 3 * 2 * 8192);
    cudaFuncSetAttribute(gemm_fp16<1,1,3>, cudaFuncAttributeMaxDynamicSharedMemorySize, 3 * 2 * 8192);
    cudaFuncSetAttribute(gemm_fp16<1,1,4>, cudaFuncAttributeMaxDynamicSharedMemorySize, 3 * 2 * 8192);
    cudaFuncSetAttribute(gemm_fp16<2,1,1>, cudaFuncAttributeMaxDynamicSharedMemorySize, 3 * 3 * 8192);

    float *QK, *Part, *Inv;
    fp16 *Eh, *Fth, *Fh, *Qh, *Kh, *Mh, *Wth, *Wtl, *PTh;
    cudaGetSymbolAddress((void**)&QK,   g_QK);
    cudaGetSymbolAddress((void**)&Part, g_part);
    cudaGetSymbolAddress((void**)&Inv,  g_inv);
    cudaGetSymbolAddress((void**)&Eh,   g_Eh);
    cudaGetSymbolAddress((void**)&Fth,  g_Fth);
    cudaGetSymbolAddress((void**)&Fh,   g_Fh);
    cudaGetSymbolAddress((void**)&Qh,   g_Qh);
    cudaGetSymbolAddress((void**)&Kh,   g_Kh);
    cudaGetSymbolAddress((void**)&Mh,   g_Mh);
    cudaGetSymbolAddress((void**)&Wth,  g_Wth);
    cudaGetSymbolAddress((void**)&Wtl,  g_Wtl);
    cudaGetSymbolAddress((void**)&PTh,  g_PTh);

    // prep
    trans1<<<dim3(HW / 32, DIM / 32, BATCH), dim3(32, 8)>>>(feat, Fth, DIM, HW);
    trans2<<<dim3(DIM / 32, DIM / 32, 1), dim3(32, 8)>>>(weight, Wth, Wtl, DIM, DIM);
    conv1<<<(BATCH * DIM * HW) / 1024, 256>>>(feat, Fh);
    conv1<<<(IDIM * DIM) / 1024, 256>>>(phi_w, PTh);
    conv1<<<(IDIM * DIM) / 1024, 256>>>(theta_w, PTh + (size_t)IDIM * DIM);

    // k1 (merged): QK[n][j] = Ft[n][:] . [phi_w;theta_w][j][:]  (M=4096, N=512, K=512)
    gemm_fp16<1,1,0><<<dim3(512 / 128, HW / 128, BATCH), 256, 3 * 2 * 8192>>>(
        Fth, nullptr, PTh, nullptr, QK, nullptr, nullptr, nullptr,
        DIM, 512, (size_t)HW * DIM, 0, (size_t)HW * 512);

    k1b_normalize<<<BATCH * HW, 256>>>();

    // k2: E[n][m] = exp(Qn . Km) + row partial sums  (M=N=4096, K=256)
    gemm_fp16<1,1,3><<<dim3(HW / 128, HW / 128, BATCH), 256, 3 * 2 * 8192>>>(
        Qh, nullptr, Kh, nullptr, nullptr, Eh, Part, nullptr,
        IDIM, HW, (size_t)HW * IDIM, (size_t)HW * IDIM, (size_t)HW * HW);

    k3b_inv<<<HW * BATCH / 8, 256>>>();

    // k4: M[n][c] = (sum_m E[n][m] * F[c][m]) * inv[n]  (M=4096, N=512, K=4096)
    gemm_fp16<1,1,4><<<dim3(DIM / 128, HW / 128, BATCH), 256, 3 * 2 * 8192>>>(
        Eh, nullptr, Fh, nullptr, nullptr, Mh, nullptr, Inv,
        HW, DIM, (size_t)HW * HW, (size_t)DIM * HW, (size_t)HW * DIM);

    // k5: out[d][n] = relu((Wth+Wtl)[d][:] . Mh[n][:])   (M=512, N=4096, K=512)
    gemm_fp16<2,1,1><<<dim3(HW / 128, DIM / 128, BATCH), 256, 3 * 3 * 8192>>>(
        Wth, Wtl, Mh, nullptr, out, nullptr, nullptr, nullptr,
        DIM, HW, 0, (size_t)HW * DIM, (size_t)DIM * HW);
}

// round 13
// speedup vs baseline: 2.5295x; 1.0727x over previous
#include <cuda_runtime.h>
#include <cuda_fp16.h>
#include <cstdint>
#include <math.h>

#define BATCH 8
#define DIM   512
#define HW    4096
#define IDIM  256

typedef __half fp16;

// ---------------- device scratch (static) ----------------
__device__ fp16  g_QKh[(size_t)BATCH * HW * 512];    // raw [phi;theta] fp16 from k1
__device__ fp16  g_Eh[(size_t)BATCH * HW * HW];      // exp(scores), single fp16 plane
__device__ float g_part[(size_t)BATCH * HW * 32];    // per-CTA row partials (reused)
__device__ float g_inv[(size_t)BATCH * HW];          // 1 / rowsum
__device__ fp16  g_Fth[(size_t)BATCH * HW * DIM];    // F^T [b][n][c], 1 plane
__device__ fp16  g_Fh[(size_t)BATCH * DIM * HW];     // F [b][c][m], 1 plane
__device__ fp16  g_Qh[(size_t)BATCH * HW * IDIM];    // normalized phi
__device__ fp16  g_Kh[(size_t)BATCH * HW * IDIM];    // normalized theta
__device__ fp16  g_Mh[(size_t)BATCH * HW * DIM];     // attn out [b][n][c]
__device__ fp16  g_Wth[(size_t)DIM * DIM];           // W^T [d][c], 1 plane
__device__ fp16  g_PTh[(size_t)2 * IDIM * DIM];      // stacked [phi_w; theta_w]

// ---------------- helpers ----------------
__device__ __forceinline__ uint32_t smem_u32(const void* p) {
    uint32_t a;
    asm("{ .reg .u64 t; cvta.to.shared.u64 t, %1; cvt.u32.u64 %0, t; }" : "=r"(a) : "l"(p));
    return a;
}
__device__ __forceinline__ void cp16(uint32_t d, const void* s) {
    asm volatile("cp.async.cg.shared.global [%0], [%1], 16;" :: "r"(d), "l"(s));
}

#define LDSM4(R, addr)                                                           \
    asm volatile("ldmatrix.sync.aligned.m8n8.x4.shared.b16 {%0,%1,%2,%3}, [%4];" \
        : "=r"((R)[0]), "=r"((R)[1]), "=r"((R)[2]), "=r"((R)[3]) : "r"(addr))

#define MMA_FP16(c, a, b0, b1)                                                   \
    asm volatile(                                                                \
        "mma.sync.aligned.m16n8k16.row.col.f32.f16.f16.f32 "                     \
        "{%0,%1,%2,%3}, {%4,%5,%6,%7}, {%8,%9}, {%0,%1,%2,%3};"                  \
        : "+f"((c)[0]), "+f"((c)[1]), "+f"((c)[2]), "+f"((c)[3])                 \
        : "r"((a)[0]), "r"((a)[1]), "r"((a)[2]), "r"((a)[3]),                    \
          "r"((b0)), "r"((b1)))

// BK=32: rows are 64B (4 x 16B granules). granule q of row r stored at q ^ ((r>>1)&3).
__device__ __forceinline__ void fill_pl(uint32_t dbase, const fp16* src, int Kdim, int tid) {
    #pragma unroll
    for (int t = 0; t < 2; t++) {
        int idx = tid + t * 256;
        int row = idx >> 2, q = idx & 3;
        cp16(dbase + row * 64 + ((q ^ ((row >> 1) & 3)) << 4),
             src + (size_t)row * Kdim + q * 8);
    }
}

// ================= fp16 multi-plane NT GEMM via mma.sync + ldmatrix =================
// C[m][n] = sum_k A[m][k]*B[n][k].  NA/NB = planes per operand, lo*lo dropped.
// CTA 128x128, 8 warps (2x4) of 64x32, BK=32, cp.async 3-stage pipeline.
// MODE 0: fp32 store   1: relu fp32 store
// MODE 3: exp() + fp16 store + row partial sums (k2)
// MODE 4: row scale by Inv + fp16 store (k4)
// MODE 5: fp16 store + row partial sum-of-squares (k1)
template<int NA, int NB, int MODE>
__global__ void __launch_bounds__(256) gemm_fp16(
    const fp16* __restrict__ Ah, const fp16* __restrict__ Al,
    const fp16* __restrict__ Bh, const fp16* __restrict__ Bl,
    float* __restrict__ C, fp16* __restrict__ Ch,
    float* __restrict__ Part, const float* __restrict__ Inv,
    int Kdim, int Ncols, size_t sA, size_t sB, size_t sC)
{
    constexpr int SPS = (NA + NB) * 8192;     // stage bytes
    extern __shared__ char smem[];
    const int tid  = threadIdx.x;
    const int lane = tid & 31, wid = tid >> 5;
    const int g = lane >> 2, tg = lane & 3;
    const int wm = wid >> 2, wn = wid & 3;
    const uint32_t sb = smem_u32(smem);

    const size_t aoff = blockIdx.z * sA + (size_t)blockIdx.y * 128 * Kdim;
    const size_t boff = blockIdx.z * sB + (size_t)blockIdx.x * 128 * Kdim;
    const fp16* pA[2] = { Ah + aoff, (NA == 2) ? Al + aoff : nullptr };
    const fp16* pB[2] = { Bh + boff, (NB == 2) ? Bl + boff : nullptr };

    float acc[4][4][4];
    #pragma unroll
    for (int i = 0; i < 4; i++)
        #pragma unroll
        for (int j = 0; j < 4; j++)
            #pragma unroll
            for (int e = 0; e < 4; e++) acc[i][j][e] = 0.f;

    const int NC = Kdim >> 5;
    const int rb = lane & 15, gs = lane >> 4;
    const int swz = (rb >> 1) & 3;

    // prefetch stages 0,1
    #pragma unroll
    for (int p = 0; p < NA; p++) fill_pl(sb + p * 8192, pA[p], Kdim, tid);
    #pragma unroll
    for (int p = 0; p < NB; p++) fill_pl(sb + (NA + p) * 8192, pB[p], Kdim, tid);
    asm volatile("cp.async.commit_group;");
    if (NC > 1) {
        #pragma unroll
        for (int p = 0; p < NA; p++) fill_pl(sb + SPS + p * 8192, pA[p] + 32, Kdim, tid);
        #pragma unroll
        for (int p = 0; p < NB; p++) fill_pl(sb + SPS + (NA + p) * 8192, pB[p] + 32, Kdim, tid);
        asm volatile("cp.async.commit_group;");
    }

    int st = 0;
    for (int c = 0; c < NC; c++) {
        if (c + 2 < NC) {
            uint32_t nb = sb + ((c + 2) % 3) * SPS;
            int ko = (c + 2) * 32;
            #pragma unroll
            for (int p = 0; p < NA; p++) fill_pl(nb + p * 8192, pA[p] + ko, Kdim, tid);
            #pragma unroll
            for (int p = 0; p < NB; p++) fill_pl(nb + (NA + p) * 8192, pB[p] + ko, Kdim, tid);
            asm volatile("cp.async.commit_group;");
            asm volatile("cp.async.wait_group 2;");
        } else if (c + 2 == NC) {
            asm volatile("cp.async.wait_group 1;");
        } else {
            asm volatile("cp.async.wait_group 0;");
        }
        __syncthreads();

        uint32_t bb = sb + st * SPS;
        #pragma unroll
        for (int s = 0; s < 2; s++) {
            const int gp = (((2 * s + gs) ^ swz) << 4);
            uint32_t af[2][4][4], bf[2][2][4];
            #pragma unroll
            for (int p = 0; p < NA; p++)
                #pragma unroll
                for (int i = 0; i < 4; i++) {
                    uint32_t ra = bb + p * 8192 + (uint32_t)(wm * 64 + i * 16 + rb) * 64 + gp;
                    LDSM4(af[p][i], ra);
                }
            #pragma unroll
            for (int p = 0; p < NB; p++)
                #pragma unroll
                for (int t = 0; t < 2; t++) {
                    uint32_t rba = bb + (NA + p) * 8192 + (uint32_t)(wn * 32 + t * 16 + rb) * 64 + gp;
                    LDSM4(bf[p][t], rba);
                }
            #pragma unroll
            for (int i = 0; i < 4; i++)
                #pragma unroll
                for (int j = 0; j < 4; j++) {
                    const int t = j >> 1, u = j & 1;
                    MMA_FP16(acc[i][j], af[0][i], bf[0][t][u], bf[0][t][u + 2]);
                    if (NB == 2)
                        MMA_FP16(acc[i][j], af[0][i], bf[1][t][u], bf[1][t][u + 2]);
                    if (NA == 2)
                        MMA_FP16(acc[i][j], af[1][i], bf[0][t][u], bf[0][t][u + 2]);
                }
        }
        __syncthreads();
        if (++st == 3) st = 0;
    }

    // ---------------- epilogue ----------------
    const int row0 = blockIdx.y * 128 + wm * 64;
    const int col0 = blockIdx.x * 128 + wn * 32;
    const int bz = blockIdx.z;

    if (MODE == 3 || MODE == 5) {
        float* spart = (float*)smem;   // [128][gridDim.x partials per CTA col]
        float rsum[4][2];
        #pragma unroll
        for (int i = 0; i < 4; i++) { rsum[i][0] = 0.f; rsum[i][1] = 0.f; }
        #pragma unroll
        for (int i = 0; i < 4; i++) {
            int r0 = row0 + i * 16 + g;
            #pragma unroll
            for (int j = 0; j < 4; j++) {
                int cc = col0 + j * 8 + tg * 2;
                float e0 = acc[i][j][0], e1 = acc[i][j][1];
                float e2 = acc[i][j][2], e3 = acc[i][j][3];
                if (MODE == 3) {
                    e0 = __expf(e0); e1 = __expf(e1);
                    e2 = __expf(e2); e3 = __expf(e3);
                    rsum[i][0] += e0 + e1;
                    rsum[i][1] += e2 + e3;
                } else {
                    rsum[i][0] += e0 * e0 + e1 * e1;
                    rsum[i][1] += e2 * e2 + e3 * e3;
                }
                size_t o0 = bz * sC + (size_t)r0 * Ncols + cc;
                size_t o1 = o0 + 8 * (size_t)Ncols;
                __half2 p0; p0.x = __float2half_rn(e0); p0.y = __float2half_rn(e1);
                __half2 p1; p1.x = __float2half_rn(e2); p1.y = __float2half_rn(e3);
                *reinterpret_cast<__half2*>(Ch + o0) = p0;
                *reinterpret_cast<__half2*>(Ch + o1) = p1;
            }
        }
        #pragma unroll
        for (int i = 0; i < 4; i++) {
            #pragma unroll
            for (int h = 0; h < 2; h++) {
                float v = rsum[i][h];
                v += __shfl_xor_sync(0xffffffffu, v, 1);
                v += __shfl_xor_sync(0xffffffffu, v, 2);
                if (tg == 0)
                    spart[(wm * 64 + i * 16 + g + h * 8) * 4 + wn] = v;
            }
        }
        __syncthreads();
        if (tid < 128) {
            float4 p = *reinterpret_cast<float4*>(spart + tid * 4);
            Part[((size_t)bz * HW + blockIdx.y * 128 + tid) * gridDim.x + blockIdx.x] =
                p.x + p.y + p.z + p.w;
        }
        return;
    }

    #pragma unroll
    for (int i = 0; i < 4; i++) {
        int r0 = row0 + i * 16 + g;
        float inv0 = 1.f, inv1 = 1.f;
        if (MODE == 4) {
            inv0 = Inv[(size_t)bz * HW + r0];
            inv1 = Inv[(size_t)bz * HW + r0 + 8];
        }
        #pragma unroll
        for (int j = 0; j < 4; j++) {
            int cc = col0 + j * 8 + tg * 2;
            if (MODE == 4) {
                size_t o0 = bz * sC + (size_t)r0 * Ncols + cc;
                size_t o1 = o0 + 8 * (size_t)Ncols;
                __half2 p0, p1;
                p0.x = __float2half_rn(acc[i][j][0] * inv0);
                p0.y = __float2half_rn(acc[i][j][1] * inv0);
                p1.x = __float2half_rn(acc[i][j][2] * inv1);
                p1.y = __float2half_rn(acc[i][j][3] * inv1);
                *reinterpret_cast<__half2*>(Ch + o0) = p0;
                *reinterpret_cast<__half2*>(Ch + o1) = p1;
            } else {
                float* b0 = C + bz * sC + (size_t)r0 * Ncols + cc;
                float* b1 = b0 + 8 * (size_t)Ncols;
                float2 v0, v1;
                v0.x = acc[i][j][0]; v0.y = acc[i][j][1];
                v1.x = acc[i][j][2]; v1.y = acc[i][j][3];
                if (MODE == 1) {
                    v0.x = fmaxf(v0.x, 0.f); v0.y = fmaxf(v0.y, 0.f);
                    v1.x = fmaxf(v1.x, 0.f); v1.y = fmaxf(v1.y, 0.f);
                }
                *reinterpret_cast<float2*>(b0) = v0;
                *reinterpret_cast<float2*>(b1) = v1;
            }
        }
    }
}

// ---------------- inv rowsum (k2 partials, stride 32) ----------------
__global__ void __launch_bounds__(256) k3b_inv() {
    int wid = threadIdx.x >> 5, lane = threadIdx.x & 31;
    size_t rr = (size_t)blockIdx.x * 8 + wid;
    float v = g_part[rr * 32 + lane];
    #pragma unroll
    for (int o = 16; o > 0; o >>= 1) v += __shfl_xor_sync(0xffffffffu, v, o);
    if (lane == 0) g_inv[rr] = 1.0f / v;
}

// ---------------- normalize QKh rows -> Qh, Kh (k1 partials, stride 4) ----------------
__global__ void __launch_bounds__(256) k1d_scale() {
    size_t row = blockIdx.x;
    __shared__ float sinv[2];
    int t = threadIdx.x;
    if (t == 0) {
        const float* p = g_part + row * 4;
        sinv[0] = rsqrtf(p[0] + p[1]);
        sinv[1] = rsqrtf(p[2] + p[3]);
    }
    __syncthreads();
    float s = sinv[t >> 7];
    __half2 v = reinterpret_cast<const __half2*>(g_QKh)[row * 256 + t];
    float2 f = __half22float2(v);
    __half2 r;
    r.x = __float2half_rn(f.x * s);
    r.y = __float2half_rn(f.y * s);
    if (t < 128)
        reinterpret_cast<__half2*>(g_Qh)[row * 128 + t] = r;
    else
        reinterpret_cast<__half2*>(g_Kh)[row * 128 + (t - 128)] = r;
}

// ---------------- feat -> Fth (transposed fp16) + Fh (straight fp16), one read ----------------
__global__ void __launch_bounds__(256) trans_dual(const float* __restrict__ in,
                                                  fp16* __restrict__ oth,
                                                  fp16* __restrict__ ostr,
                                                  int R, int C) {
    __shared__ float t[32][33];
    int b = blockIdx.z;
    const float* ib = in + (size_t)b * R * C;
    size_t ob = (size_t)b * R * C;
    int c0 = blockIdx.x * 32, r0 = blockIdx.y * 32;
    int x = threadIdx.x, y = threadIdx.y;
    #pragma unroll
    for (int i = 0; i < 32; i += 8) {
        float v = ib[(size_t)(r0 + y + i) * C + c0 + x];
        t[y + i][x] = v;
        ostr[ob + (size_t)(r0 + y + i) * C + c0 + x] = __float2half_rn(v);
    }
    __syncthreads();
    #pragma unroll
    for (int i = 0; i < 32; i += 8)
        oth[ob + (size_t)(c0 + y + i) * R + r0 + x] = __float2half_rn(t[x][y + i]);
}

// ---------------- transpose, 1-plane fp16 ----------------
__global__ void __launch_bounds__(256) trans1(const float* __restrict__ in,
                                              fp16* __restrict__ oh, int R, int C) {
    __shared__ float t[32][33];
    int b = blockIdx.z;
    const float* ib = in + (size_t)b * R * C;
    size_t ob = (size_t)b * R * C;
    int c0 = blockIdx.x * 32, r0 = blockIdx.y * 32;
    int x = threadIdx.x, y = threadIdx.y;
    #pragma unroll
    for (int i = 0; i < 32; i += 8)
        t[y + i][x] = ib[(size_t)(r0 + y + i) * C + c0 + x];
    __syncthreads();
    #pragma unroll
    for (int i = 0; i < 32; i += 8)
        oh[ob + (size_t)(c0 + y + i) * R + r0 + x] = __float2half_rn(t[x][y + i]);
}

// ---------------- elementwise fp16 conversion ----------------
__global__ void __launch_bounds__(256) conv1(const float* __restrict__ in,
                                             fp16* __restrict__ oh) {
    size_t i0 = ((size_t)blockIdx.x * 256 + threadIdx.x) * 4;
    float4 v = *reinterpret_cast<const float4*>(in + i0);
    __half2 a, b;
    a.x = __float2half_rn(v.x); a.y = __float2half_rn(v.y);
    b.x = __float2half_rn(v.z); b.y = __float2half_rn(v.w);
    *reinterpret_cast<__half2*>(oh + i0)     = a;
    *reinterpret_cast<__half2*>(oh + i0 + 2) = b;
}

// ---------------- launch ----------------
extern "C" void kernel_launch(void* const* d_in, const int* in_sizes, int n_in,
                              void* d_out, int out_size) {
    const float* feat    = (const float*)d_in[0];   // [8, 512, 64, 64]
    const float* phi_w   = (const float*)d_in[1];   // [256, 512]
    const float* theta_w = (const float*)d_in[2];   // [256, 512]
    const float* weight  = (const float*)d_in[3];   // [512, 512]
    float* out = (float*)d_out;                     // [8, 512, 64, 64]

    cudaFuncSetAttribute(gemm_fp16<1,1,5>, cudaFuncAttributeMaxDynamicSharedMemorySize, 3 * 2 * 8192);
    cudaFuncSetAttribute(gemm_fp16<1,1,3>, cudaFuncAttributeMaxDynamicSharedMemorySize, 3 * 2 * 8192);
    cudaFuncSetAttribute(gemm_fp16<1,1,4>, cudaFuncAttributeMaxDynamicSharedMemorySize, 3 * 2 * 8192);
    cudaFuncSetAttribute(gemm_fp16<1,1,1>, cudaFuncAttributeMaxDynamicSharedMemorySize, 3 * 2 * 8192);

    float *Part, *Inv;
    fp16 *QKh, *Eh, *Fth, *Fh, *Qh, *Kh, *Mh, *Wth, *PTh;
    cudaGetSymbolAddress((void**)&QKh,  g_QKh);
    cudaGetSymbolAddress((void**)&Part, g_part);
    cudaGetSymbolAddress((void**)&Inv,  g_inv);
    cudaGetSymbolAddress((void**)&Eh,   g_Eh);
    cudaGetSymbolAddress((void**)&Fth,  g_Fth);
    cudaGetSymbolAddress((void**)&Fh,   g_Fh);
    cudaGetSymbolAddress((void**)&Qh,   g_Qh);
    cudaGetSymbolAddress((void**)&Kh,   g_Kh);
    cudaGetSymbolAddress((void**)&Mh,   g_Mh);
    cudaGetSymbolAddress((void**)&Wth,  g_Wth);
    cudaGetSymbolAddress((void**)&PTh,  g_PTh);

    // prep: one pass over feat -> Fth + Fh; W^T; stacked projection weights
    trans_dual<<<dim3(HW / 32, DIM / 32, BATCH), dim3(32, 8)>>>(feat, Fth, Fh, DIM, HW);
    trans1<<<dim3(DIM / 32, DIM / 32, 1), dim3(32, 8)>>>(weight, Wth, DIM, DIM);
    conv1<<<(IDIM * DIM) / 1024, 256>>>(phi_w, PTh);
    conv1<<<(IDIM * DIM) / 1024, 256>>>(theta_w, PTh + (size_t)IDIM * DIM);

    // k1: QKh[n][j] = Ft[n][:] . [phi_w;theta_w][j][:]  + partial sumsq  (M=4096, N=512, K=512)
    gemm_fp16<1,1,5><<<dim3(512 / 128, HW / 128, BATCH), 256, 3 * 2 * 8192>>>(
        Fth, nullptr, PTh, nullptr, nullptr, QKh, Part, nullptr,
        DIM, 512, (size_t)HW * DIM, 0, (size_t)HW * 512);

    // normalize rows -> Qh, Kh
    k1d_scale<<<BATCH * HW, 256>>>();

    // k2: E[n][m] = exp(Qn . Km) + row partial sums  (M=N=4096, K=256)
    gemm_fp16<1,1,3><<<dim3(HW / 128, HW / 128, BATCH), 256, 3 * 2 * 8192>>>(
        Qh, nullptr, Kh, nullptr, nullptr, Eh, Part, nullptr,
        IDIM, HW, (size_t)HW * IDIM, (size_t)HW * IDIM, (size_t)HW * HW);

    k3b_inv<<<HW * BATCH / 8, 256>>>();

    // k4: M[n][c] = (sum_m E[n][m] * F[c][m]) * inv[n]  (M=4096, N=512, K=4096)
    gemm_fp16<1,1,4><<<dim3(DIM / 128, HW / 128, BATCH), 256, 3 * 2 * 8192>>>(
        Eh, nullptr, Fh, nullptr, nullptr, Mh, nullptr, Inv,
        HW, DIM, (size_t)HW * HW, (size_t)DIM * HW, (size_t)HW * DIM);

    // k5: out[d][n] = relu(Wth[d][:] . Mh[n][:])   (M=512, N=4096, K=512)
    gemm_fp16<1,1,1><<<dim3(HW / 128, DIM / 128, BATCH), 256, 3 * 2 * 8192>>>(
        Wth, nullptr, Mh, nullptr, out, nullptr, nullptr, nullptr,
        DIM, HW, 0, (size_t)HW * DIM, (size_t)DIM * HW);
}

// round 14
// speedup vs baseline: 2.7139x; 1.0729x over previous
#include <cuda_runtime.h>
#include <cuda_fp16.h>
#include <cstdint>
#include <math.h>

#define BATCH 8
#define DIM   512
#define HW    4096
#define IDIM  256

typedef __half fp16;

// ---------------- device scratch (static) ----------------
__device__ fp16  g_QKh[(size_t)BATCH * HW * 512];    // raw [phi;theta] fp16 from k1
__device__ fp16  g_Eh[(size_t)BATCH * HW * HW];      // exp(scores), single fp16 plane
__device__ float g_part[(size_t)BATCH * HW * 32];    // per-CTA row partials (reused)
__device__ float g_inv[(size_t)BATCH * HW];          // 1 / rowsum
__device__ fp16  g_Fth[(size_t)BATCH * HW * DIM];    // F^T [b][n][c], 1 plane
__device__ fp16  g_Fh[(size_t)BATCH * DIM * HW];     // F [b][c][m], 1 plane
__device__ fp16  g_Qh[(size_t)BATCH * HW * IDIM];    // normalized phi (pre-scaled by log2e)
__device__ fp16  g_Kh[(size_t)BATCH * HW * IDIM];    // normalized theta
__device__ fp16  g_Mh[(size_t)BATCH * HW * DIM];     // attn out [b][n][c]
__device__ fp16  g_Wth[(size_t)DIM * DIM];           // W^T [d][c], 1 plane
__device__ fp16  g_PTh[(size_t)2 * IDIM * DIM];      // stacked [phi_w; theta_w]

// ---------------- helpers ----------------
__device__ __forceinline__ uint32_t smem_u32(const void* p) {
    uint32_t a;
    asm("{ .reg .u64 t; cvta.to.shared.u64 t, %1; cvt.u32.u64 %0, t; }" : "=r"(a) : "l"(p));
    return a;
}
__device__ __forceinline__ void cp16(uint32_t d, const void* s) {
    asm volatile("cp.async.cg.shared.global [%0], [%1], 16;" :: "r"(d), "l"(s));
}

#define LDSM4(R, addr)                                                           \
    asm volatile("ldmatrix.sync.aligned.m8n8.x4.shared.b16 {%0,%1,%2,%3}, [%4];" \
        : "=r"((R)[0]), "=r"((R)[1]), "=r"((R)[2]), "=r"((R)[3]) : "r"(addr))

#define MMA_FP16(c, a, b0, b1)                                                   \
    asm volatile(                                                                \
        "mma.sync.aligned.m16n8k16.row.col.f32.f16.f16.f32 "                     \
        "{%0,%1,%2,%3}, {%4,%5,%6,%7}, {%8,%9}, {%0,%1,%2,%3};"                  \
        : "+f"((c)[0]), "+f"((c)[1]), "+f"((c)[2]), "+f"((c)[3])                 \
        : "r"((a)[0]), "r"((a)[1]), "r"((a)[2]), "r"((a)[3]),                    \
          "r"((b0)), "r"((b1)))

// BK=32: rows are 64B (4 x 16B granules). granule q of row r stored at q ^ ((r>>1)&3).
__device__ __forceinline__ void fill_pl(uint32_t dbase, const fp16* src, int Kdim, int tid) {
    #pragma unroll
    for (int t = 0; t < 2; t++) {
        int idx = tid + t * 256;
        int row = idx >> 2, q = idx & 3;
        cp16(dbase + row * 64 + ((q ^ ((row >> 1) & 3)) << 4),
             src + (size_t)row * Kdim + q * 8);
    }
}

// ================= fp16 multi-plane NT GEMM via mma.sync + ldmatrix =================
// C[m][n] = sum_k A[m][k]*B[n][k].  NA/NB = planes per operand, lo*lo dropped.
// CTA 128x128, 8 warps (2x4) of 64x32, BK=32, 4-stage cp.async pipeline with
// prefetch distance 2 -> only ONE __syncthreads per K-chunk (fill target was
// last read two iterations ago; the start-of-iter barrier orders it).
// MODE 0: fp32 store   1: relu fp32 store
// MODE 3: exp2() + fp16 store + row partial sums (k2; Q pre-scaled by log2e)
// MODE 4: row scale by Inv + fp16 store (k4)
// MODE 5: fp16 store + row partial sum-of-squares (k1)
template<int NA, int NB, int MODE>
__global__ void __launch_bounds__(256) gemm_fp16(
    const fp16* __restrict__ Ah, const fp16* __restrict__ Al,
    const fp16* __restrict__ Bh, const fp16* __restrict__ Bl,
    float* __restrict__ C, fp16* __restrict__ Ch,
    float* __restrict__ Part, const float* __restrict__ Inv,
    int Kdim, int Ncols, size_t sA, size_t sB, size_t sC)
{
    constexpr int SPS = (NA + NB) * 8192;     // stage bytes
    extern __shared__ char smem[];
    const int tid  = threadIdx.x;
    const int lane = tid & 31, wid = tid >> 5;
    const int g = lane >> 2, tg = lane & 3;
    const int wm = wid >> 2, wn = wid & 3;
    const uint32_t sb = smem_u32(smem);

    const size_t aoff = blockIdx.z * sA + (size_t)blockIdx.y * 128 * Kdim;
    const size_t boff = blockIdx.z * sB + (size_t)blockIdx.x * 128 * Kdim;
    const fp16* pA[2] = { Ah + aoff, (NA == 2) ? Al + aoff : nullptr };
    const fp16* pB[2] = { Bh + boff, (NB == 2) ? Bl + boff : nullptr };

    float acc[4][4][4];
    #pragma unroll
    for (int i = 0; i < 4; i++)
        #pragma unroll
        for (int j = 0; j < 4; j++)
            #pragma unroll
            for (int e = 0; e < 4; e++) acc[i][j][e] = 0.f;

    const int NC = Kdim >> 5;
    const int rb = lane & 15, gs = lane >> 4;
    const int swz = (rb >> 1) & 3;

    // prologue: fill stages 0,1 (separate commit groups)
    #pragma unroll
    for (int p = 0; p < NA; p++) fill_pl(sb + p * 8192, pA[p], Kdim, tid);
    #pragma unroll
    for (int p = 0; p < NB; p++) fill_pl(sb + (NA + p) * 8192, pB[p], Kdim, tid);
    asm volatile("cp.async.commit_group;");
    #pragma unroll
    for (int p = 0; p < NA; p++) fill_pl(sb + SPS + p * 8192, pA[p] + 32, Kdim, tid);
    #pragma unroll
    for (int p = 0; p < NB; p++) fill_pl(sb + SPS + (NA + p) * 8192, pB[p] + 32, Kdim, tid);
    asm volatile("cp.async.commit_group;");

    for (int c = 0; c < NC; c++) {
        if (c + 2 < NC) {
            uint32_t nb = sb + ((c + 2) & 3) * SPS;
            int ko = (c + 2) * 32;
            #pragma unroll
            for (int p = 0; p < NA; p++) fill_pl(nb + p * 8192, pA[p] + ko, Kdim, tid);
            #pragma unroll
            for (int p = 0; p < NB; p++) fill_pl(nb + (NA + p) * 8192, pB[p] + ko, Kdim, tid);
            asm volatile("cp.async.commit_group;");
            asm volatile("cp.async.wait_group 2;");
        } else if (c + 2 == NC) {
            asm volatile("cp.async.wait_group 1;");
        } else {
            asm volatile("cp.async.wait_group 0;");
        }
        __syncthreads();   // the ONLY barrier per chunk

        uint32_t bb = sb + (c & 3) * SPS;
        #pragma unroll
        for (int s = 0; s < 2; s++) {
            const int gp = (((2 * s + gs) ^ swz) << 4);
            uint32_t af[2][4][4], bf[2][2][4];
            #pragma unroll
            for (int p = 0; p < NA; p++)
                #pragma unroll
                for (int i = 0; i < 4; i++) {
                    uint32_t ra = bb + p * 8192 + (uint32_t)(wm * 64 + i * 16 + rb) * 64 + gp;
                    LDSM4(af[p][i], ra);
                }
            #pragma unroll
            for (int p = 0; p < NB; p++)
                #pragma unroll
                for (int t = 0; t < 2; t++) {
                    uint32_t rba = bb + (NA + p) * 8192 + (uint32_t)(wn * 32 + t * 16 + rb) * 64 + gp;
                    LDSM4(bf[p][t], rba);
                }
            #pragma unroll
            for (int i = 0; i < 4; i++)
                #pragma unroll
                for (int j = 0; j < 4; j++) {
                    const int t = j >> 1, u = j & 1;
                    MMA_FP16(acc[i][j], af[0][i], bf[0][t][u], bf[0][t][u + 2]);
                    if (NB == 2)
                        MMA_FP16(acc[i][j], af[0][i], bf[1][t][u], bf[1][t][u + 2]);
                    if (NA == 2)
                        MMA_FP16(acc[i][j], af[1][i], bf[0][t][u], bf[0][t][u + 2]);
                }
        }
    }

    // ---------------- epilogue ----------------
    const int row0 = blockIdx.y * 128 + wm * 64;
    const int col0 = blockIdx.x * 128 + wn * 32;
    const int bz = blockIdx.z;

    if (MODE == 3 || MODE == 5) {
        __syncthreads();               // spart aliases stage 0; wait for all MMA reads
        float* spart = (float*)smem;   // [128][4]
        float rsum[4][2];
        #pragma unroll
        for (int i = 0; i < 4; i++) { rsum[i][0] = 0.f; rsum[i][1] = 0.f; }
        #pragma unroll
        for (int i = 0; i < 4; i++) {
            int r0 = row0 + i * 16 + g;
            #pragma unroll
            for (int j = 0; j < 4; j++) {
                int cc = col0 + j * 8 + tg * 2;
                float e0 = acc[i][j][0], e1 = acc[i][j][1];
                float e2 = acc[i][j][2], e3 = acc[i][j][3];
                if (MODE == 3) {
                    e0 = exp2f(e0); e1 = exp2f(e1);
                    e2 = exp2f(e2); e3 = exp2f(e3);
                    rsum[i][0] += e0 + e1;
                    rsum[i][1] += e2 + e3;
                } else {
                    rsum[i][0] += e0 * e0 + e1 * e1;
                    rsum[i][1] += e2 * e2 + e3 * e3;
                }
                size_t o0 = bz * sC + (size_t)r0 * Ncols + cc;
                size_t o1 = o0 + 8 * (size_t)Ncols;
                __half2 p0; p0.x = __float2half_rn(e0); p0.y = __float2half_rn(e1);
                __half2 p1; p1.x = __float2half_rn(e2); p1.y = __float2half_rn(e3);
                *reinterpret_cast<__half2*>(Ch + o0) = p0;
                *reinterpret_cast<__half2*>(Ch + o1) = p1;
            }
        }
        #pragma unroll
        for (int i = 0; i < 4; i++) {
            #pragma unroll
            for (int h = 0; h < 2; h++) {
                float v = rsum[i][h];
                v += __shfl_xor_sync(0xffffffffu, v, 1);
                v += __shfl_xor_sync(0xffffffffu, v, 2);
                if (tg == 0)
                    spart[(wm * 64 + i * 16 + g + h * 8) * 4 + wn] = v;
            }
        }
        __syncthreads();
        if (tid < 128) {
            float4 p = *reinterpret_cast<float4*>(spart + tid * 4);
            Part[((size_t)bz * HW + blockIdx.y * 128 + tid) * gridDim.x + blockIdx.x] =
                p.x + p.y + p.z + p.w;
        }
        return;
    }

    #pragma unroll
    for (int i = 0; i < 4; i++) {
        int r0 = row0 + i * 16 + g;
        float inv0 = 1.f, inv1 = 1.f;
        if (MODE == 4) {
            inv0 = Inv[(size_t)bz * HW + r0];
            inv1 = Inv[(size_t)bz * HW + r0 + 8];
        }
        #pragma unroll
        for (int j = 0; j < 4; j++) {
            int cc = col0 + j * 8 + tg * 2;
            if (MODE == 4) {
                size_t o0 = bz * sC + (size_t)r0 * Ncols + cc;
                size_t o1 = o0 + 8 * (size_t)Ncols;
                __half2 p0, p1;
                p0.x = __float2half_rn(acc[i][j][0] * inv0);
                p0.y = __float2half_rn(acc[i][j][1] * inv0);
                p1.x = __float2half_rn(acc[i][j][2] * inv1);
                p1.y = __float2half_rn(acc[i][j][3] * inv1);
                *reinterpret_cast<__half2*>(Ch + o0) = p0;
                *reinterpret_cast<__half2*>(Ch + o1) = p1;
            } else {
                float* b0 = C + bz * sC + (size_t)r0 * Ncols + cc;
                float* b1 = b0 + 8 * (size_t)Ncols;
                float2 v0, v1;
                v0.x = acc[i][j][0]; v0.y = acc[i][j][1];
                v1.x = acc[i][j][2]; v1.y = acc[i][j][3];
                if (MODE == 1) {
                    v0.x = fmaxf(v0.x, 0.f); v0.y = fmaxf(v0.y, 0.f);
                    v1.x = fmaxf(v1.x, 0.f); v1.y = fmaxf(v1.y, 0.f);
                }
                *reinterpret_cast<float2*>(b0) = v0;
                *reinterpret_cast<float2*>(b1) = v1;
            }
        }
    }
}

// ---------------- inv rowsum (k2 partials, stride 32) ----------------
__global__ void __launch_bounds__(256) k3b_inv() {
    int wid = threadIdx.x >> 5, lane = threadIdx.x & 31;
    size_t rr = (size_t)blockIdx.x * 8 + wid;
    float v = g_part[rr * 32 + lane];
    #pragma unroll
    for (int o = 16; o > 0; o >>= 1) v += __shfl_xor_sync(0xffffffffu, v, o);
    if (lane == 0) g_inv[rr] = 1.0f / v;
}

// ---------------- normalize QKh rows -> Qh (x log2e), Kh ----------------
__global__ void __launch_bounds__(256) k1d_scale() {
    size_t row = blockIdx.x;
    __shared__ float sinv[2];
    int t = threadIdx.x;
    if (t == 0) {
        const float* p = g_part + row * 4;
        sinv[0] = rsqrtf(p[0] + p[1]) * 1.4426950408889634f;  // phi: fold log2e
        sinv[1] = rsqrtf(p[2] + p[3]);                        // theta
    }
    __syncthreads();
    float s = sinv[t >> 7];
    __half2 v = reinterpret_cast<const __half2*>(g_QKh)[row * 256 + t];
    float2 f = __half22float2(v);
    __half2 r;
    r.x = __float2half_rn(f.x * s);
    r.y = __float2half_rn(f.y * s);
    if (t < 128)
        reinterpret_cast<__half2*>(g_Qh)[row * 128 + t] = r;
    else
        reinterpret_cast<__half2*>(g_Kh)[row * 128 + (t - 128)] = r;
}

// ---------------- feat -> Fth (transposed fp16) + Fh (straight fp16), one read ----------------
__global__ void __launch_bounds__(256) trans_dual(const float* __restrict__ in,
                                                  fp16* __restrict__ oth,
                                                  fp16* __restrict__ ostr,
                                                  int R, int C) {
    __shared__ float t[32][33];
    int b = blockIdx.z;
    const float* ib = in + (size_t)b * R * C;
    size_t ob = (size_t)b * R * C;
    int c0 = blockIdx.x * 32, r0 = blockIdx.y * 32;
    int x = threadIdx.x, y = threadIdx.y;
    #pragma unroll
    for (int i = 0; i < 32; i += 8) {
        float v = ib[(size_t)(r0 + y + i) * C + c0 + x];
        t[y + i][x] = v;
        ostr[ob + (size_t)(r0 + y + i) * C + c0 + x] = __float2half_rn(v);
    }
    __syncthreads();
    #pragma unroll
    for (int i = 0; i < 32; i += 8)
        oth[ob + (size_t)(c0 + y + i) * R + r0 + x] = __float2half_rn(t[x][y + i]);
}

// ---------------- transpose, 1-plane fp16 ----------------
__global__ void __launch_bounds__(256) trans1(const float* __restrict__ in,
                                              fp16* __restrict__ oh, int R, int C) {
    __shared__ float t[32][33];
    int b = blockIdx.z;
    const float* ib = in + (size_t)b * R * C;
    size_t ob = (size_t)b * R * C;
    int c0 = blockIdx.x * 32, r0 = blockIdx.y * 32;
    int x = threadIdx.x, y = threadIdx.y;
    #pragma unroll
    for (int i = 0; i < 32; i += 8)
        t[y + i][x] = ib[(size_t)(r0 + y + i) * C + c0 + x];
    __syncthreads();
    #pragma unroll
    for (int i = 0; i < 32; i += 8)
        oh[ob + (size_t)(c0 + y + i) * R + r0 + x] = __float2half_rn(t[x][y + i]);
}

// ---------------- elementwise fp16 conversion ----------------
__global__ void __launch_bounds__(256) conv1(const float* __restrict__ in,
                                             fp16* __restrict__ oh) {
    size_t i0 = ((size_t)blockIdx.x * 256 + threadIdx.x) * 4;
    float4 v = *reinterpret_cast<const float4*>(in + i0);
    __half2 a, b;
    a.x = __float2half_rn(v.x); a.y = __float2half_rn(v.y);
    b.x = __float2half_rn(v.z); b.y = __float2half_rn(v.w);
    *reinterpret_cast<__half2*>(oh + i0)     = a;
    *reinterpret_cast<__half2*>(oh + i0 + 2) = b;
}

// ---------------- launch ----------------
extern "C" void kernel_launch(void* const* d_in, const int* in_sizes, int n_in,
                              void* d_out, int out_size) {
    const float* feat    = (const float*)d_in[0];   // [8, 512, 64, 64]
    const float* phi_w   = (const float*)d_in[1];   // [256, 512]
    const float* theta_w = (const float*)d_in[2];   // [256, 512]
    const float* weight  = (const float*)d_in[3];   // [512, 512]
    float* out = (float*)d_out;                     // [8, 512, 64, 64]

    cudaFuncSetAttribute(gemm_fp16<1,1,5>, cudaFuncAttributeMaxDynamicSharedMemorySize, 4 * 2 * 8192);
    cudaFuncSetAttribute(gemm_fp16<1,1,3>, cudaFuncAttributeMaxDynamicSharedMemorySize, 4 * 2 * 8192);
    cudaFuncSetAttribute(gemm_fp16<1,1,4>, cudaFuncAttributeMaxDynamicSharedMemorySize, 4 * 2 * 8192);
    cudaFuncSetAttribute(gemm_fp16<1,1,1>, cudaFuncAttributeMaxDynamicSharedMemorySize, 4 * 2 * 8192);

    float *Part, *Inv;
    fp16 *QKh, *Eh, *Fth, *Fh, *Qh, *Kh, *Mh, *Wth, *PTh;
    cudaGetSymbolAddress((void**)&QKh,  g_QKh);
    cudaGetSymbolAddress((void**)&Part, g_part);
    cudaGetSymbolAddress((void**)&Inv,  g_inv);
    cudaGetSymbolAddress((void**)&Eh,   g_Eh);
    cudaGetSymbolAddress((void**)&Fth,  g_Fth);
    cudaGetSymbolAddress((void**)&Fh,   g_Fh);
    cudaGetSymbolAddress((void**)&Qh,   g_Qh);
    cudaGetSymbolAddress((void**)&Kh,   g_Kh);
    cudaGetSymbolAddress((void**)&Mh,   g_Mh);
    cudaGetSymbolAddress((void**)&Wth,  g_Wth);
    cudaGetSymbolAddress((void**)&PTh,  g_PTh);

    // prep: one pass over feat -> Fth + Fh; W^T; stacked projection weights
    trans_dual<<<dim3(HW / 32, DIM / 32, BATCH), dim3(32, 8)>>>(feat, Fth, Fh, DIM, HW);
    trans1<<<dim3(DIM / 32, DIM / 32, 1), dim3(32, 8)>>>(weight, Wth, DIM, DIM);
    conv1<<<(IDIM * DIM) / 1024, 256>>>(phi_w, PTh);
    conv1<<<(IDIM * DIM) / 1024, 256>>>(theta_w, PTh + (size_t)IDIM * DIM);

    // k1: QKh[n][j] = Ft[n][:] . [phi_w;theta_w][j][:]  + partial sumsq  (M=4096, N=512, K=512)
    gemm_fp16<1,1,5><<<dim3(512 / 128, HW / 128, BATCH), 256, 4 * 2 * 8192>>>(
        Fth, nullptr, PTh, nullptr, nullptr, QKh, Part, nullptr,
        DIM, 512, (size_t)HW * DIM, 0, (size_t)HW * 512);

    // normalize rows -> Qh (pre-scaled by log2e), Kh
    k1d_scale<<<BATCH * HW, 256>>>();

    // k2: E[n][m] = exp2(Qs . K) = exp(q.k) + row partial sums  (M=N=4096, K=256)
    gemm_fp16<1,1,3><<<dim3(HW / 128, HW / 128, BATCH), 256, 4 * 2 * 8192>>>(
        Qh, nullptr, Kh, nullptr, nullptr, Eh, Part, nullptr,
        IDIM, HW, (size_t)HW * IDIM, (size_t)HW * IDIM, (size_t)HW * HW);

    k3b_inv<<<HW * BATCH / 8, 256>>>();

    // k4: M[n][c] = (sum_m E[n][m] * F[c][m]) * inv[n]  (M=4096, N=512, K=4096)
    gemm_fp16<1,1,4><<<dim3(DIM / 128, HW / 128, BATCH), 256, 4 * 2 * 8192>>>(
        Eh, nullptr, Fh, nullptr, nullptr, Mh, nullptr, Inv,
        HW, DIM, (size_t)HW * HW, (size_t)DIM * HW, (size_t)HW * DIM);

    // k5: out[d][n] = relu(Wth[d][:] . Mh[n][:])   (M=512, N=4096, K=512)
    gemm_fp16<1,1,1><<<dim3(HW / 128, DIM / 128, BATCH), 256, 4 * 2 * 8192>>>(
        Wth, nullptr, Mh, nullptr, out, nullptr, nullptr, nullptr,
        DIM, HW, 0, (size_t)HW * DIM, (size_t)DIM * HW);
}